// round 13
// baseline (speedup 1.0000x reference)
#include <cuda_runtime.h>
#include <cuda_bf16.h>
#include <math.h>
#include <stdint.h>

#define NB 2
#define SL 512
#define DM 768
#define DI 1536
#define DS 16
#define XD 80
#define DR 48
#define BL (NB*SL)

// ---------------- scratch ----------------
__device__ float g_xres[BL*DM];
__device__ float g_xz  [BL*2*DI];
__device__ float g_xc  [BL*DI];
__device__ float g_xdbl[BL*XD];
__device__ float g_dt  [BL*DI];
__device__ float g_u   [BL*DI];
__device__ float g_P   [NB*SL*SL];
__device__ float g_W   [NB*SL*DS];
__device__ float g_G   [NB*SL*DS*DS];
__device__ float g_M   [NB*SL*DS*DS];
__device__ __align__(16) __nv_bfloat16 g_Ah[BL*DI];
__device__ __align__(16) __nv_bfloat16 g_Al[BL*DI];
__device__ __align__(16) __nv_bfloat16 g_Bh[2*DI*DM];
__device__ __align__(16) __nv_bfloat16 g_Bl[2*DI*DM];

// ================= helpers =================
__device__ __forceinline__ uint32_t smem_u32(const void* p) {
    uint32_t a;
    asm("{ .reg .u64 t; cvta.to.shared.u64 t, %1; cvt.u32.u64 %0, t; }" : "=r"(a) : "l"(p));
    return a;
}

__device__ __forceinline__ void split1(float v, __nv_bfloat16& h, __nv_bfloat16& l) {
    h = __float2bfloat16_rn(v);
    l = __float2bfloat16_rn(v - __bfloat162float(h));
}

__device__ __forceinline__ void cvt_split(float4 v, uint2& hi, uint2& lo) {
    __nv_bfloat162 h0 = __floats2bfloat162_rn(v.x, v.y);
    __nv_bfloat162 h1 = __floats2bfloat162_rn(v.z, v.w);
    float rx = v.x - __bfloat162float(__low2bfloat16(h0));
    float ry = v.y - __bfloat162float(__high2bfloat16(h0));
    float rz = v.z - __bfloat162float(__low2bfloat16(h1));
    float rw = v.w - __bfloat162float(__high2bfloat16(h1));
    __nv_bfloat162 l0 = __floats2bfloat162_rn(rx, ry);
    __nv_bfloat162 l1 = __floats2bfloat162_rn(rz, rw);
    hi.x = *(uint32_t*)&h0; hi.y = *(uint32_t*)&h1;
    lo.x = *(uint32_t*)&l0; lo.y = *(uint32_t*)&l1;
}

__global__ void split_k(const float4* __restrict__ src, uint2* __restrict__ hi,
                        uint2* __restrict__ lo, int n4)
{
    int i = blockIdx.x*256 + threadIdx.x;
    if (i < n4) {
        uint2 h, l;
        cvt_split(src[i], h, l);
        hi[i] = h; lo[i] = l;
    }
}

__global__ void zero3_k(float4* __restrict__ a, int na,
                        float4* __restrict__ b, int nb,
                        float4* __restrict__ c, int nc)
{
    int i = blockIdx.x*256 + threadIdx.x;
    float4 z = make_float4(0.f, 0.f, 0.f, 0.f);
    if (i < na) a[i] = z;
    else if (i < na + nb) b[i - na] = z;
    else if (i < na + nb + nc) c[i - na - nb] = z;
}

__global__ void copy_k(const float* __restrict__ src, float* __restrict__ dst, int n)
{
    int i = blockIdx.x*blockDim.x + threadIdx.x;
    if (i < n) dst[i] = src[i];
}

__device__ __forceinline__ void ldsm4(uint32_t a, uint32_t& r0, uint32_t& r1,
                                      uint32_t& r2, uint32_t& r3) {
    asm volatile("ldmatrix.sync.aligned.m8n8.x4.shared.b16 {%0,%1,%2,%3}, [%4];"
                 : "=r"(r0), "=r"(r1), "=r"(r2), "=r"(r3) : "r"(a));
}

__device__ __forceinline__ void mma16816(float* c, const uint32_t* a, const uint32_t* b) {
    asm volatile(
        "mma.sync.aligned.m16n8k16.row.col.f32.bf16.bf16.f32 "
        "{%0,%1,%2,%3}, {%4,%5,%6,%7}, {%8,%9}, {%0,%1,%2,%3};"
        : "+f"(c[0]), "+f"(c[1]), "+f"(c[2]), "+f"(c[3])
        : "r"(a[0]), "r"(a[1]), "r"(a[2]), "r"(a[3]), "r"(b[0]), "r"(b[1]));
}

__device__ __forceinline__ void cp16(uint32_t saddr, const void* g, int srcsize) {
    asm volatile("cp.async.cg.shared.global [%0], [%1], 16, %2;"
                 :: "r"(saddr), "l"(g), "r"(srcsize) : "memory");
}
#define CP_COMMIT() asm volatile("cp.async.commit_group;" ::: "memory")
#define CP_WAIT1()  asm volatile("cp.async.wait_group 1;" ::: "memory")

// ================= tensor-core GEMM, split-K, atomic accumulate, cp.async x2 ====
// C[m,n] += sum_{k in slice} A[m,k]*B[n,k]; A=Ah+Al, B=Bh+Bl (3-term product).
// grid.z = nbatch*nsplit; slice length Ks (multiple of 64).
// mode bit1: triangular skip. C must be pre-initialized (zeros or residual).
#define HG_SMEM (2*4*128*64*2)   // 128 KB: 2 stages x (Ah,Al,Bh,Bl)[128][64] bf16

__global__ __launch_bounds__(512, 1)
void hgemm_nt(const __nv_bfloat16* __restrict__ Ah, const __nv_bfloat16* __restrict__ Al,
              const __nv_bfloat16* __restrict__ Bh, const __nv_bfloat16* __restrict__ Bl,
              float* __restrict__ C,
              int M, int N, int Ks, int lda, int ldb,
              long sA, long sB, long sC, int mode, int nsplit)
{
    extern __shared__ char smraw[];
    const int m0 = blockIdx.y * 128, n0 = blockIdx.x * 128;
    if ((mode & 2) && (n0 > m0)) return;

    const int bz = blockIdx.z / nsplit;
    const int koff = (blockIdx.z % nsplit) * Ks;
    Ah += bz * sA + koff; Al += bz * sA + koff;
    Bh += bz * sB + koff; Bl += bz * sB + koff;
    C  += bz * sC;

    const uint32_t sb = smem_u32(smraw);

    const int tid = threadIdx.x;
    const int wid = tid >> 5, lane = tid & 31;
    const int wm = (wid & 3) * 32;
    const int wn = (wid >> 2) * 32;

    const int srow = tid >> 2, sseg = tid & 3;
    const __nv_bfloat16* Ahp = Ah + (long)(m0 + srow) * lda + sseg * 16;
    const __nv_bfloat16* Alp = Al + (long)(m0 + srow) * lda + sseg * 16;
    const __nv_bfloat16* Bhp = Bh + (long)(n0 + srow) * ldb + sseg * 16;
    const __nv_bfloat16* Blp = Bl + (long)(n0 + srow) * ldb + sseg * 16;
    const bool bval = (n0 + srow) < N;
    const int bsz = bval ? 16 : 0;

    uint32_t soff[2];
    #pragma unroll
    for (int i = 0; i < 2; i++) {
        uint32_t cc = (uint32_t)(sseg * 2 + i);
        soff[i] = (uint32_t)srow * 128 + ((cc ^ (srow & 7)) * 16);
    }

    const int nch = Ks / 64;

    // issue stage fill for chunk c into stage s
    auto issue = [&](int s, int c) {
        const uint32_t st = sb + (uint32_t)s * 65536;
        const __nv_bfloat16* ahn = Ahp + c * 64;
        const __nv_bfloat16* aln = Alp + c * 64;
        const __nv_bfloat16* bhn = Bhp + c * 64;
        const __nv_bfloat16* bln = Blp + c * 64;
        #pragma unroll
        for (int i = 0; i < 2; i++) {
            cp16(st + soff[i],         ahn + i * 8, 16);
            cp16(st + 16384 + soff[i], aln + i * 8, 16);
            cp16(st + 32768 + soff[i], bhn + i * 8, bsz);
            cp16(st + 49152 + soff[i], bln + i * 8, bsz);
        }
    };

    issue(0, 0); CP_COMMIT();
    if (nch > 1) issue(1, 1);
    CP_COMMIT();

    const int arow_l = lane & 15, acc_l = lane >> 4;
    const int brow_l = (lane & 7) + ((lane >> 4) << 3), bcc_l = (lane >> 3) & 1;

    float acc[2][4][4];
    #pragma unroll
    for (int mt = 0; mt < 2; mt++)
        #pragma unroll
        for (int nt = 0; nt < 4; nt++)
            #pragma unroll
            for (int q = 0; q < 4; q++) acc[mt][nt][q] = 0.f;

    for (int c = 0; c < nch; c++) {
        const int s = c & 1;
        const uint32_t Ahu = sb + (uint32_t)s * 65536;
        const uint32_t Alu = Ahu + 16384, Bhu = Ahu + 32768, Blu = Ahu + 49152;

        CP_WAIT1();
        __syncthreads();

        #pragma unroll
        for (int ks = 0; ks < 4; ks++) {
            uint32_t ah[2][4], al[2][4], bh[2][4], bl[2][4];
            #pragma unroll
            for (int mt = 0; mt < 2; mt++) {
                int row = wm + mt * 16 + arow_l;
                uint32_t cc = (uint32_t)(2 * ks + acc_l);
                uint32_t off = (uint32_t)row * 128 + ((cc ^ (row & 7)) * 16);
                ldsm4(Ahu + off, ah[mt][0], ah[mt][1], ah[mt][2], ah[mt][3]);
                ldsm4(Alu + off, al[mt][0], al[mt][1], al[mt][2], al[mt][3]);
            }
            #pragma unroll
            for (int p = 0; p < 2; p++) {
                int row = wn + p * 16 + brow_l;
                uint32_t cc = (uint32_t)(2 * ks + bcc_l);
                uint32_t off = (uint32_t)row * 128 + ((cc ^ (row & 7)) * 16);
                ldsm4(Bhu + off, bh[p][0], bh[p][1], bh[p][2], bh[p][3]);
                ldsm4(Blu + off, bl[p][0], bl[p][1], bl[p][2], bl[p][3]);
            }
            #pragma unroll
            for (int mt = 0; mt < 2; mt++) {
                #pragma unroll
                for (int nt = 0; nt < 4; nt++) {
                    uint32_t bfr[2] = { bh[nt >> 1][2 * (nt & 1)], bh[nt >> 1][2 * (nt & 1) + 1] };
                    uint32_t blr[2] = { bl[nt >> 1][2 * (nt & 1)], bl[nt >> 1][2 * (nt & 1) + 1] };
                    mma16816(acc[mt][nt], ah[mt], bfr);
                    mma16816(acc[mt][nt], al[mt], bfr);
                    mma16816(acc[mt][nt], ah[mt], blr);
                }
            }
        }
        __syncthreads();
        if (c + 2 < nch) issue(s, c + 2);
        CP_COMMIT();
    }

    #pragma unroll
    for (int mt = 0; mt < 2; mt++) {
        #pragma unroll
        for (int nt = 0; nt < 4; nt++) {
            int mrow = m0 + wm + mt * 16 + (lane >> 2);
            int ncol = n0 + wn + nt * 8 + 2 * (lane & 3);
            float* d = acc[mt][nt];
            if (ncol < N) {
                long o0 = (long)mrow * N + ncol;
                long o1 = (long)(mrow + 8) * N + ncol;
                atomicAdd(&C[o0],     d[0]);
                atomicAdd(&C[o0 + 1], d[1]);
                atomicAdd(&C[o1],     d[2]);
                atomicAdd(&C[o1 + 1], d[3]);
            }
        }
    }
}

// ---------------- fused small kernels ----------------
__global__ void rmsnorm_k(const float* __restrict__ X, const float* __restrict__ w,
                          float* __restrict__ Yf,
                          __nv_bfloat16* __restrict__ Hh, __nv_bfloat16* __restrict__ Hl)
{
    int row = blockIdx.x;
    const float* xr = X + (long)row*DM;
    float s = 0.f;
    for (int c = threadIdx.x; c < DM; c += 256) { float v = xr[c]; s = fmaf(v, v, s); }
    __shared__ float red[256];
    red[threadIdx.x] = s; __syncthreads();
    for (int o = 128; o > 0; o >>= 1) {
        if (threadIdx.x < o) red[threadIdx.x] += red[threadIdx.x + o];
        __syncthreads();
    }
    float scale = rsqrtf(red[0] * (1.0f/DM) + 1e-5f);
    for (int c = threadIdx.x; c < DM; c += 256) {
        float v = xr[c] * scale * w[c];
        if (Yf) Yf[(long)row*DM + c] = v;
        if (Hh) {
            __nv_bfloat16 h, l; split1(v, h, l);
            Hh[(long)row*DM + c] = h;
            Hl[(long)row*DM + c] = l;
        }
    }
}

__global__ void conv_silu_k(const float* __restrict__ xz, const float* __restrict__ cw,
                            const float* __restrict__ cb, float* __restrict__ xc,
                            __nv_bfloat16* __restrict__ Hh, __nv_bfloat16* __restrict__ Hl)
{
    int d   = blockIdx.x*256 + threadIdx.x;
    int row = blockIdx.y;
    int l   = row & (SL-1);
    const float4 w4 = *(const float4*)(cw + d*4);
    float acc = cb[d];
    if (l >= 3) acc = fmaf(xz[(long)(row-3)*2*DI + d], w4.x, acc);
    if (l >= 2) acc = fmaf(xz[(long)(row-2)*2*DI + d], w4.y, acc);
    if (l >= 1) acc = fmaf(xz[(long)(row-1)*2*DI + d], w4.z, acc);
    acc = fmaf(xz[(long)row*2*DI + d], w4.w, acc);
    float sig = 1.f / (1.f + __expf(-acc));
    float v = acc * sig;
    long o = (long)row*DI + d;
    xc[o] = v;
    __nv_bfloat16 h, lo; split1(v, h, lo);
    Hh[o] = h; Hl[o] = lo;
}

__global__ void dt_epi_k(float* __restrict__ dt, const float* __restrict__ dtb,
                         const float* __restrict__ xc, float* __restrict__ u,
                         __nv_bfloat16* __restrict__ Hh, __nv_bfloat16* __restrict__ Hl)
{
    int i = blockIdx.x*256 + threadIdx.x;
    int d = i % DI;
    float x = dt[i] + dtb[d];
    float sp = (x > 20.f) ? x : log1pf(__expf(x));
    dt[i] = sp;
    float uv = sp * xc[i];
    u[i] = uv;
    __nv_bfloat16 h, l; split1(uv, h, l);
    Hh[i] = h; Hl[i] = l;
}

// ---------------- SIMT 64x64 SGEMM (dt_proj: K=48) ----------------
__global__ __launch_bounds__(256) void sgemm_nt(
    const float* __restrict__ A, const float* __restrict__ B,
    float* __restrict__ C,
    int M, int N, int K, int lda, int ldb)
{
    __shared__ float As[16][64];
    __shared__ float Bs[16][64];
    const int tid  = threadIdx.x;
    const int m0   = blockIdx.y*64, n0 = blockIdx.x*64;
    const int lrow = tid >> 2, lc4 = (tid & 3) << 2;
    const int tx   = tid & 15,  ty = tid >> 4;

    float acc[4][4] = {};
    const float* Aptr = A + (long)(m0 + lrow)*lda + lc4;
    const float* Bptr = B + (long)(n0 + lrow)*ldb + lc4;
    const bool bvalid = (n0 + lrow) < N;

    for (int k0 = 0; k0 < K; k0 += 16) {
        float4 av = *(const float4*)(Aptr + k0);
        float4 bvv = make_float4(0.f, 0.f, 0.f, 0.f);
        if (bvalid) bvv = *(const float4*)(Bptr + k0);
        __syncthreads();
        As[lc4+0][lrow]=av.x; As[lc4+1][lrow]=av.y; As[lc4+2][lrow]=av.z; As[lc4+3][lrow]=av.w;
        Bs[lc4+0][lrow]=bvv.x; Bs[lc4+1][lrow]=bvv.y; Bs[lc4+2][lrow]=bvv.z; Bs[lc4+3][lrow]=bvv.w;
        __syncthreads();
        #pragma unroll
        for (int k = 0; k < 16; k++) {
            float4 a = *(const float4*)(&As[k][ty<<2]);
            float4 b = *(const float4*)(&Bs[k][tx<<2]);
            acc[0][0]=fmaf(a.x,b.x,acc[0][0]); acc[0][1]=fmaf(a.x,b.y,acc[0][1]);
            acc[0][2]=fmaf(a.x,b.z,acc[0][2]); acc[0][3]=fmaf(a.x,b.w,acc[0][3]);
            acc[1][0]=fmaf(a.y,b.x,acc[1][0]); acc[1][1]=fmaf(a.y,b.y,acc[1][1]);
            acc[1][2]=fmaf(a.y,b.z,acc[1][2]); acc[1][3]=fmaf(a.y,b.w,acc[1][3]);
            acc[2][0]=fmaf(a.z,b.x,acc[2][0]); acc[2][1]=fmaf(a.z,b.y,acc[2][1]);
            acc[2][2]=fmaf(a.z,b.z,acc[2][2]); acc[2][3]=fmaf(a.z,b.w,acc[2][3]);
            acc[3][0]=fmaf(a.w,b.x,acc[3][0]); acc[3][1]=fmaf(a.w,b.y,acc[3][1]);
            acc[3][2]=fmaf(a.w,b.z,acc[3][2]); acc[3][3]=fmaf(a.w,b.w,acc[3][3]);
        }
    }
    #pragma unroll
    for (int i = 0; i < 4; i++) {
        int m = m0 + (ty<<2) + i;
        #pragma unroll
        for (int j = 0; j < 4; j++) {
            int n = n0 + (tx<<2) + j;
            if (n < N) C[(long)m*N + n] = acc[i][j];
        }
    }
}

// ---------------- w_t = sum_{s<t} beta^{t-1-s} P[s,t] b_s ----------------
__global__ void wk_k(const float* __restrict__ P, const float* __restrict__ xdbl,
                     float* __restrict__ W)
{
    int t = blockIdx.x, b = blockIdx.y, tid = threadIdx.x;
    const float* Prow = P + ((long)b*SL + t)*SL;
    float acc[16];
    #pragma unroll
    for (int n = 0; n < 16; n++) acc[n] = 0.f;

    float decay = exp2f((float)tid * -0.15200309344504995f);
    const float step = 1.3901084526083426e-06f;
    for (int s = t - 1 - tid; s >= 0; s -= 128) {
        float p = Prow[s] * decay;
        const float* bm = xdbl + ((long)b*SL + s)*XD + DR;
        float4 b0 = *(const float4*)(bm);
        float4 b1 = *(const float4*)(bm + 4);
        float4 b2 = *(const float4*)(bm + 8);
        float4 b3 = *(const float4*)(bm + 12);
        acc[0]=fmaf(p,b0.x,acc[0]);  acc[1]=fmaf(p,b0.y,acc[1]);
        acc[2]=fmaf(p,b0.z,acc[2]);  acc[3]=fmaf(p,b0.w,acc[3]);
        acc[4]=fmaf(p,b1.x,acc[4]);  acc[5]=fmaf(p,b1.y,acc[5]);
        acc[6]=fmaf(p,b1.z,acc[6]);  acc[7]=fmaf(p,b1.w,acc[7]);
        acc[8]=fmaf(p,b2.x,acc[8]);  acc[9]=fmaf(p,b2.y,acc[9]);
        acc[10]=fmaf(p,b2.z,acc[10]); acc[11]=fmaf(p,b2.w,acc[11]);
        acc[12]=fmaf(p,b3.x,acc[12]); acc[13]=fmaf(p,b3.y,acc[13]);
        acc[14]=fmaf(p,b3.z,acc[14]); acc[15]=fmaf(p,b3.w,acc[15]);
        decay *= step;
    }
    __shared__ float red[128][17];
    #pragma unroll
    for (int n = 0; n < 16; n++) red[tid][n] = acc[n];
    __syncthreads();
    for (int o = 64; o > 0; o >>= 1) {
        if (tid < o) {
            #pragma unroll
            for (int n = 0; n < 16; n++) red[tid][n] += red[tid+o][n];
        }
        __syncthreads();
    }
    if (tid < 16) W[((long)b*SL + t)*DS + tid] = red[0][tid];
}

// ---------------- G scan (Kogge-Stone over t, decay beta^2) ----------------
__global__ void gscan_k(const float* __restrict__ xdbl, const float* __restrict__ W,
                        const float* __restrict__ P, float* __restrict__ G)
{
    int nm = blockIdx.x;
    int b  = blockIdx.y;
    int n  = nm >> 4, m = nm & 15;
    int t  = threadIdx.x;
    long row = (long)b*SL + t;

    float bn  = xdbl[row*XD + DR + n];
    float bmv = xdbl[row*XD + DR + m];
    float wn  = W[row*DS + n], wm = W[row*DS + m];
    float ptt = P[row*SL + t];
    float g = 0.9f*(bn*wm + wn*bmv) + ptt*bn*bmv;

    __shared__ float sm[SL];
    sm[t] = g; __syncthreads();
    float lam = 0.81f;
    for (int o = 1; o < SL; o <<= 1) {
        float prev = (t >= o) ? sm[t-o] : 0.f;
        __syncthreads();
        g = fmaf(lam, prev, g);
        sm[t] = g;
        __syncthreads();
        lam *= lam;
    }
    G[row*256 + nm] = g;
}

// ---------------- N_t = (aI + b*S + c*S^2)/f ----------------
__global__ void mbuild_k(const float* __restrict__ G, float* __restrict__ Nm)
{
    int bt  = blockIdx.x;
    int tid = threadIdx.x;
    __shared__ float Gs[256], Ss[256];
    __shared__ float fsh;
    Gs[tid] = G[(long)bt*256 + tid];
    __syncthreads();
    if (tid == 0) {
        float tr = 0.f;
        #pragma unroll
        for (int i = 0; i < 16; i++) tr += Gs[i*17];
        fsh = sqrtf(tr) + 1e-7f;
    }
    __syncthreads();
    float f = fsh, fi2 = 1.f/(f*f);
    Ss[tid] = Gs[tid] * fi2;
    __syncthreads();
    int n = tid >> 4, m = tid & 15;
    float s2 = 0.f;
    #pragma unroll
    for (int k = 0; k < 16; k++) s2 = fmaf(Ss[n*16 + k], Ss[k*16 + m], s2);
    float sv = Ss[tid];
    float Mv = fmaf(-4.775f, sv, 2.0315f*s2);
    if (n == m) Mv += 3.4445f;
    Nm[(long)bt*256 + tid] = Mv / f;
}

// ---------------- sequential scan: warp-autonomous, 4 channels/warp ----------
__global__ void __launch_bounds__(32)
scan_k(const float* __restrict__ Nm, const float* __restrict__ xdbl,
       const float* __restrict__ U, const float* __restrict__ DT,
       const float* __restrict__ A_log, const float* __restrict__ xc,
       const float* __restrict__ xz, const float* __restrict__ Dp,
       __nv_bfloat16* __restrict__ Yh, __nv_bfloat16* __restrict__ Yl)
{
    const int b    = blockIdx.y;
    const int lane = threadIdx.x;           // 32
    const int sub  = lane >> 3, l8 = lane & 7, n0 = 2*l8;
    const int ch   = blockIdx.x*4 + sub;

    const float An0 = -__expf(A_log[ch*DS + n0]);
    const float An1 = -__expf(A_log[ch*DS + n0 + 1]);
    const float Dv  = Dp[ch];

    __shared__ float Ns[2][256];
    const float* Nbase = Nm + (long)b*SL*256;
    const long xrow = (long)b*SL*XD + DR;

    // N prefetch (stage 0 = t0, regs = t1)
    *(float4*)&Ns[0][lane*8]     = *(const float4*)(Nbase + lane*8);
    *(float4*)&Ns[0][lane*8 + 4] = *(const float4*)(Nbase + lane*8 + 4);
    float4 nva = *(const float4*)(Nbase + 256 + lane*8);
    float4 nvb = *(const float4*)(Nbase + 256 + lane*8 + 4);

    // b/C prefetch (pure registers)
    const float* xd0 = xdbl + xrow;
    float2 bCur = *(const float2*)(xd0 + n0);
    float2 cCur = *(const float2*)(xd0 + DS + n0);
    float2 bNxt = *(const float2*)(xd0 + XD + n0);
    float2 cNxt = *(const float2*)(xd0 + XD + DS + n0);

    const long base_di = (long)b*SL*DI + ch;
    const long base_z  = (long)b*SL*2*DI + DI + ch;
    float uCur  = U [base_di],      dtCur = DT[base_di];
    float xcCur = xc[base_di],      zCur  = xz[base_z];
    float uNxt  = U [base_di + DI], dtNxt = DT[base_di + DI];
    float xcNxt = xc[base_di + DI], zNxt  = xz[base_z + 2*DI];

    float v0=0.f, v1=0.f, h0=0.f, h1=0.f;

    for (int t = 0; t < SL; t++) {
        const int s = t & 1;
        __syncwarp();
        if (t + 1 < SL) {
            *(float4*)&Ns[s^1][lane*8]     = nva;
            *(float4*)&Ns[s^1][lane*8 + 4] = nvb;
        }
        if (t + 2 < SL) {
            nva = *(const float4*)(Nbase + (long)(t+2)*256 + lane*8);
            nvb = *(const float4*)(Nbase + (long)(t+2)*256 + lane*8 + 4);
        }
        const float ut = uCur, dtt = dtCur, xcv = xcCur, zv = zCur;
        const float2 bt = bCur, ct = cCur;
        uCur = uNxt; dtCur = dtNxt; xcCur = xcNxt; zCur = zNxt;
        bCur = bNxt; cCur = cNxt;
        if (t + 2 < SL) {
            const float* xd2 = xdbl + xrow + (long)(t+2)*XD;
            bNxt = *(const float2*)(xd2 + n0);
            cNxt = *(const float2*)(xd2 + DS + n0);
            uNxt  = U [base_di + (long)(t+2)*DI];
            dtNxt = DT[base_di + (long)(t+2)*DI];
            xcNxt = xc[base_di + (long)(t+2)*DI];
            zNxt  = xz[base_z + (long)(t+2)*2*DI];
        }

        v0 = fmaf(0.9f, v0, ut*bt.x);
        v1 = fmaf(0.9f, v1, ut*bt.y);
        float dA0 = __expf(dtt*An0), dA1 = __expf(dtt*An1);

        float a0e=0.f, a1e=0.f, a0o=0.f, a1o=0.f;
        #pragma unroll
        for (int j = 0; j < 8; j += 2) {
            float vm0 = __shfl_sync(0xffffffffu, v0, j, 8);
            float vm1 = __shfl_sync(0xffffffffu, v1, j, 8);
            float2 r0 = *(const float2*)&Ns[s][(2*j)*16 + n0];
            float2 r1 = *(const float2*)&Ns[s][(2*j+1)*16 + n0];
            a0e = fmaf(vm0, r0.x, a0e); a1e = fmaf(vm0, r0.y, a1e);
            a0e = fmaf(vm1, r1.x, a0e); a1e = fmaf(vm1, r1.y, a1e);
            float wm0 = __shfl_sync(0xffffffffu, v0, j+1, 8);
            float wm1 = __shfl_sync(0xffffffffu, v1, j+1, 8);
            float2 q0 = *(const float2*)&Ns[s][(2*j+2)*16 + n0];
            float2 q1 = *(const float2*)&Ns[s][(2*j+3)*16 + n0];
            a0o = fmaf(wm0, q0.x, a0o); a1o = fmaf(wm0, q0.y, a1o);
            a0o = fmaf(wm1, q1.x, a0o); a1o = fmaf(wm1, q1.y, a1o);
        }
        h0 = fmaf(dA0, h0, a0e + a0o);
        h1 = fmaf(dA1, h1, a1e + a1o);

        float yv = h0*ct.x + h1*ct.y;
        yv += __shfl_xor_sync(0xffffffffu, yv, 4, 8);
        yv += __shfl_xor_sync(0xffffffffu, yv, 2, 8);
        yv += __shfl_xor_sync(0xffffffffu, yv, 1, 8);
        if (l8 == 0) {
            float sig = 1.f / (1.f + __expf(-zv));
            float yo = (yv + Dv*xcv) * (zv*sig);
            __nv_bfloat16 hh, ll; split1(yo, hh, ll);
            long o = base_di + (long)t*DI;
            Yh[o] = hh; Yl[o] = ll;
        }
    }
}

// ---------------- launcher ----------------
extern "C" void kernel_launch(void* const* d_in, const int* in_sizes, int n_in,
                              void* d_out, int out_size)
{
    const float* x    = (const float*)d_in[0];
    const float* inw  = (const float*)d_in[1];
    const float* cw   = (const float*)d_in[2];
    const float* cb   = (const float*)d_in[3];
    const float* xpw  = (const float*)d_in[4];
    const float* dtw  = (const float*)d_in[5];
    const float* dtb  = (const float*)d_in[6];
    const float* alog = (const float*)d_in[7];
    const float* Dpar = (const float*)d_in[8];
    const float* outw = (const float*)d_in[9];
    const float* nw   = (const float*)d_in[10];
    const float* fnw  = (const float*)d_in[11];
    float* out = (float*)d_out;

    float *xres,*xz,*xc,*xdbl,*dt,*u,*P,*W,*G,*Mm;
    __nv_bfloat16 *Ah,*Al,*Bh,*Bl;
    cudaGetSymbolAddress((void**)&xres, g_xres);
    cudaGetSymbolAddress((void**)&xz,   g_xz);
    cudaGetSymbolAddress((void**)&xc,   g_xc);
    cudaGetSymbolAddress((void**)&xdbl, g_xdbl);
    cudaGetSymbolAddress((void**)&dt,   g_dt);
    cudaGetSymbolAddress((void**)&u,    g_u);
    cudaGetSymbolAddress((void**)&P,    g_P);
    cudaGetSymbolAddress((void**)&W,    g_W);
    cudaGetSymbolAddress((void**)&G,    g_G);
    cudaGetSymbolAddress((void**)&Mm,   g_M);
    cudaGetSymbolAddress((void**)&Ah,   g_Ah);
    cudaGetSymbolAddress((void**)&Al,   g_Al);
    cudaGetSymbolAddress((void**)&Bh,   g_Bh);
    cudaGetSymbolAddress((void**)&Bl,   g_Bl);

    cudaFuncSetAttribute(hgemm_nt, cudaFuncAttributeMaxDynamicSharedMemorySize, HG_SMEM);

    copy_k<<<(BL*DM + 255)/256, 256>>>(x, xres, BL*DM);

    const int nz = BL*2*DI/4 + BL*XD/4 + NB*SL*SL/4;

    for (int layer = 0; layer < 2; layer++) {
        const float* inw_l  = inw  + (long)layer*2*DI*DM;
        const float* cw_l   = cw   + (long)layer*DI*4;
        const float* cb_l   = cb   + (long)layer*DI;
        const float* xpw_l  = xpw  + (long)layer*XD*DI;
        const float* dtw_l  = dtw  + (long)layer*DI*DR;
        const float* dtb_l  = dtb  + (long)layer*DI;
        const float* alog_l = alog + (long)layer*DI*DS;
        const float* Dp_l   = Dpar + (long)layer*DI;
        const float* outw_l = outw + (long)layer*DM*DI;
        const float* nw_l   = nw   + (long)layer*DM;

        rmsnorm_k<<<BL, 256>>>(xres, nw_l, nullptr, Ah, Al);
        split_k<<<(2*DI*DM/4 + 255)/256, 256>>>((const float4*)inw_l, (uint2*)Bh, (uint2*)Bl, 2*DI*DM/4);
        zero3_k<<<(nz + 255)/256, 256>>>((float4*)xz, BL*2*DI/4,
                                         (float4*)xdbl, BL*XD/4,
                                         (float4*)P, NB*SL*SL/4);
        // xz += xn @ in_w^T : M=1024, N=3072, K=768, split-K 2
        hgemm_nt<<<dim3(2*DI/128, BL/128, 2), 512, HG_SMEM>>>(
            Ah, Al, Bh, Bl, xz, BL, 2*DI, 384, DM, DM, 0, 0, 0, 0, 2);

        conv_silu_k<<<dim3(DI/256, BL), 256>>>(xz, cw_l, cb_l, xc, Ah, Al);

        split_k<<<(XD*DI/4 + 255)/256, 256>>>((const float4*)xpw_l, (uint2*)Bh, (uint2*)Bl, XD*DI/4);
        // xdbl += xc @ xp_w^T : M=1024, N=80, K=1536, split-K 6
        hgemm_nt<<<dim3(1, BL/128, 6), 512, HG_SMEM>>>(
            Ah, Al, Bh, Bl, xdbl, BL, XD, 256, DI, DI, 0, 0, 0, 0, 6);

        // dt_pre = dt_lr @ dtp_w^T : M=1024, N=1536, K=48 (SIMT)
        sgemm_nt<<<dim3(DI/64, BL/64), 256>>>(xdbl, dtw_l, dt, BL, DI, DR, XD, DR);

        dt_epi_k<<<BL*DI/256, 256>>>(dt, dtb_l, xc, u, Ah, Al);

        // P += U U^T : M=N=512, K=1536, batched NB, lower-tri, split-K 4
        hgemm_nt<<<dim3(SL/128, SL/128, NB*4), 512, HG_SMEM>>>(
            Ah, Al, Ah, Al, P, SL, SL, 384, DI, DI,
            (long)SL*DI, (long)SL*DI, (long)SL*SL, 2, 4);

        wk_k<<<dim3(SL, NB), 128>>>(P, xdbl, W);
        gscan_k<<<dim3(256, NB), 512>>>(xdbl, W, P, G);
        mbuild_k<<<NB*SL, 256>>>(G, Mm);
        scan_k<<<dim3(DI/4, NB), 32>>>(Mm, xdbl, u, dt, alog_l, xc, xz, Dp_l, Ah, Al);

        split_k<<<(DM*DI/4 + 255)/256, 256>>>((const float4*)outw_l, (uint2*)Bh, (uint2*)Bl, DM*DI/4);
        // xres += y @ out_w^T : M=1024, N=768, K=1536, split-K 3 (residual in place)
        hgemm_nt<<<dim3(DM/128, BL/128, 3), 512, HG_SMEM>>>(
            Ah, Al, Bh, Bl, xres, BL, DM, 512, DI, DI, 0, 0, 0, 0, 3);
    }

    rmsnorm_k<<<BL, 256>>>(xres, fnw, out, nullptr, nullptr);
}

// round 14
// speedup vs baseline: 1.3449x; 1.3449x over previous
#include <cuda_runtime.h>
#include <cuda_bf16.h>
#include <math.h>
#include <stdint.h>

#define NB 2
#define SL 512
#define DM 768
#define DI 1536
#define DS 16
#define XD 80
#define DR 48
#define BL (NB*SL)

// ---------------- scratch ----------------
__device__ float g_xres[BL*DM];
__device__ float g_xz  [BL*2*DI];
__device__ float g_xc  [BL*DI];
__device__ float g_xdbl[BL*XD];
__device__ float g_dt  [BL*DI];
__device__ float g_u   [BL*DI];
__device__ float g_P   [NB*SL*SL];
__device__ float g_W   [NB*SL*DS];
__device__ float g_G   [NB*SL*DS*DS];
__device__ float g_M   [NB*SL*DS*DS];
__device__ __align__(16) __nv_bfloat16 g_Ah[BL*DI];
__device__ __align__(16) __nv_bfloat16 g_Al[BL*DI];
__device__ __align__(16) __nv_bfloat16 g_Bh[2*DI*DM];
__device__ __align__(16) __nv_bfloat16 g_Bl[2*DI*DM];

// ================= helpers =================
__device__ __forceinline__ uint32_t smem_u32(const void* p) {
    uint32_t a;
    asm("{ .reg .u64 t; cvta.to.shared.u64 t, %1; cvt.u32.u64 %0, t; }" : "=r"(a) : "l"(p));
    return a;
}

__device__ __forceinline__ void split1(float v, __nv_bfloat16& h, __nv_bfloat16& l) {
    h = __float2bfloat16_rn(v);
    l = __float2bfloat16_rn(v - __bfloat162float(h));
}

__device__ __forceinline__ void cvt_split(float4 v, uint2& hi, uint2& lo) {
    __nv_bfloat162 h0 = __floats2bfloat162_rn(v.x, v.y);
    __nv_bfloat162 h1 = __floats2bfloat162_rn(v.z, v.w);
    float rx = v.x - __bfloat162float(__low2bfloat16(h0));
    float ry = v.y - __bfloat162float(__high2bfloat16(h0));
    float rz = v.z - __bfloat162float(__low2bfloat16(h1));
    float rw = v.w - __bfloat162float(__high2bfloat16(h1));
    __nv_bfloat162 l0 = __floats2bfloat162_rn(rx, ry);
    __nv_bfloat162 l1 = __floats2bfloat162_rn(rz, rw);
    hi.x = *(uint32_t*)&h0; hi.y = *(uint32_t*)&h1;
    lo.x = *(uint32_t*)&l0; lo.y = *(uint32_t*)&l1;
}

__global__ void split_k(const float4* __restrict__ src, uint2* __restrict__ hi,
                        uint2* __restrict__ lo, int n4)
{
    int i = blockIdx.x*256 + threadIdx.x;
    if (i < n4) {
        uint2 h, l;
        cvt_split(src[i], h, l);
        hi[i] = h; lo[i] = l;
    }
}

__global__ void zero3_k(float4* __restrict__ a, int na,
                        float4* __restrict__ b, int nb,
                        float4* __restrict__ c, int nc)
{
    int i = blockIdx.x*256 + threadIdx.x;
    float4 z = make_float4(0.f, 0.f, 0.f, 0.f);
    if (i < na) a[i] = z;
    else if (i < na + nb) b[i - na] = z;
    else if (i < na + nb + nc) c[i - na - nb] = z;
}

__global__ void copy_k(const float* __restrict__ src, float* __restrict__ dst, int n)
{
    int i = blockIdx.x*blockDim.x + threadIdx.x;
    if (i < n) dst[i] = src[i];
}

__device__ __forceinline__ void ldsm4(uint32_t a, uint32_t& r0, uint32_t& r1,
                                      uint32_t& r2, uint32_t& r3) {
    asm volatile("ldmatrix.sync.aligned.m8n8.x4.shared.b16 {%0,%1,%2,%3}, [%4];"
                 : "=r"(r0), "=r"(r1), "=r"(r2), "=r"(r3) : "r"(a));
}

__device__ __forceinline__ void mma16816(float* c, const uint32_t* a, const uint32_t* b) {
    asm volatile(
        "mma.sync.aligned.m16n8k16.row.col.f32.bf16.bf16.f32 "
        "{%0,%1,%2,%3}, {%4,%5,%6,%7}, {%8,%9}, {%0,%1,%2,%3};"
        : "+f"(c[0]), "+f"(c[1]), "+f"(c[2]), "+f"(c[3])
        : "r"(a[0]), "r"(a[1]), "r"(a[2]), "r"(a[3]), "r"(b[0]), "r"(b[1]));
}

// ================= tensor-core GEMM, split-K, atomic accumulate =================
// (R12 winning version: register-prefetch staging, single-buffered smem)
// C[m,n] += sum_{k in slice} A[m,k]*B[n,k]; A=Ah+Al, B=Bh+Bl (3-term product).
// grid.z = nbatch*nsplit; slice length Ks (multiple of 64).
// mode bit1: triangular skip. C must be pre-initialized (zeros or residual).
#define HG_SMEM (4*128*64*2)   // 64 KB

__global__ __launch_bounds__(512, 1)
void hgemm_nt(const __nv_bfloat16* __restrict__ Ah, const __nv_bfloat16* __restrict__ Al,
              const __nv_bfloat16* __restrict__ Bh, const __nv_bfloat16* __restrict__ Bl,
              float* __restrict__ C,
              int M, int N, int Ks, int lda, int ldb,
              long sA, long sB, long sC, int mode, int nsplit)
{
    extern __shared__ char smraw[];
    const int m0 = blockIdx.y * 128, n0 = blockIdx.x * 128;
    if ((mode & 2) && (n0 > m0)) return;

    const int bz = blockIdx.z / nsplit;
    const int koff = (blockIdx.z % nsplit) * Ks;
    Ah += bz * sA + koff; Al += bz * sA + koff;
    Bh += bz * sB + koff; Bl += bz * sB + koff;
    C  += bz * sC;

    char* const AhP = smraw;
    char* const AlP = smraw + 16384;
    char* const BhP = smraw + 32768;
    char* const BlP = smraw + 49152;
    const uint32_t Ahu = smem_u32(AhP), Alu = Ahu + 16384, Bhu = Ahu + 32768, Blu = Ahu + 49152;

    const int tid = threadIdx.x;
    const int wid = tid >> 5, lane = tid & 31;
    const int wm = (wid & 3) * 32;
    const int wn = (wid >> 2) * 32;

    const int srow = tid >> 2, sseg = tid & 3;
    const __nv_bfloat16* Ahp = Ah + (long)(m0 + srow) * lda + sseg * 16;
    const __nv_bfloat16* Alp = Al + (long)(m0 + srow) * lda + sseg * 16;
    const __nv_bfloat16* Bhp = Bh + (long)(n0 + srow) * ldb + sseg * 16;
    const __nv_bfloat16* Blp = Bl + (long)(n0 + srow) * ldb + sseg * 16;
    const bool bval = (n0 + srow) < N;

    uint32_t soff[2];
    #pragma unroll
    for (int i = 0; i < 2; i++) {
        uint32_t cc = (uint32_t)(sseg * 2 + i);
        soff[i] = (uint32_t)srow * 128 + ((cc ^ (srow & 7)) * 16);
    }

    const int arow_l = lane & 15, acc_l = lane >> 4;
    const int brow_l = (lane & 7) + ((lane >> 4) << 3), bcc_l = (lane >> 3) & 1;

    float acc[2][4][4];
    #pragma unroll
    for (int mt = 0; mt < 2; mt++)
        #pragma unroll
        for (int nt = 0; nt < 4; nt++)
            #pragma unroll
            for (int q = 0; q < 4; q++) acc[mt][nt][q] = 0.f;

    const int nch = Ks / 64;
    const uint4 zero4 = make_uint4(0, 0, 0, 0);
    uint4 rah[2], ral[2], rbh[2], rbl[2];
    #pragma unroll
    for (int i = 0; i < 2; i++) {
        rah[i] = *(const uint4*)(Ahp + i * 8);
        ral[i] = *(const uint4*)(Alp + i * 8);
        rbh[i] = bval ? *(const uint4*)(Bhp + i * 8) : zero4;
        rbl[i] = bval ? *(const uint4*)(Blp + i * 8) : zero4;
    }

    for (int c = 0; c < nch; c++) {
        #pragma unroll
        for (int i = 0; i < 2; i++) {
            *(uint4*)(AhP + soff[i]) = rah[i];
            *(uint4*)(AlP + soff[i]) = ral[i];
            *(uint4*)(BhP + soff[i]) = rbh[i];
            *(uint4*)(BlP + soff[i]) = rbl[i];
        }
        __syncthreads();

        if (c + 1 < nch) {
            const __nv_bfloat16* ahn = Ahp + (c + 1) * 64;
            const __nv_bfloat16* aln = Alp + (c + 1) * 64;
            const __nv_bfloat16* bhn = Bhp + (c + 1) * 64;
            const __nv_bfloat16* bln = Blp + (c + 1) * 64;
            #pragma unroll
            for (int i = 0; i < 2; i++) {
                rah[i] = *(const uint4*)(ahn + i * 8);
                ral[i] = *(const uint4*)(aln + i * 8);
                rbh[i] = bval ? *(const uint4*)(bhn + i * 8) : zero4;
                rbl[i] = bval ? *(const uint4*)(bln + i * 8) : zero4;
            }
        }

        #pragma unroll
        for (int ks = 0; ks < 4; ks++) {
            uint32_t ah[2][4], al[2][4], bh[2][4], bl[2][4];
            #pragma unroll
            for (int mt = 0; mt < 2; mt++) {
                int row = wm + mt * 16 + arow_l;
                uint32_t cc = (uint32_t)(2 * ks + acc_l);
                uint32_t off = (uint32_t)row * 128 + ((cc ^ (row & 7)) * 16);
                ldsm4(Ahu + off, ah[mt][0], ah[mt][1], ah[mt][2], ah[mt][3]);
                ldsm4(Alu + off, al[mt][0], al[mt][1], al[mt][2], al[mt][3]);
            }
            #pragma unroll
            for (int p = 0; p < 2; p++) {
                int row = wn + p * 16 + brow_l;
                uint32_t cc = (uint32_t)(2 * ks + bcc_l);
                uint32_t off = (uint32_t)row * 128 + ((cc ^ (row & 7)) * 16);
                ldsm4(Bhu + off, bh[p][0], bh[p][1], bh[p][2], bh[p][3]);
                ldsm4(Blu + off, bl[p][0], bl[p][1], bl[p][2], bl[p][3]);
            }
            #pragma unroll
            for (int mt = 0; mt < 2; mt++) {
                #pragma unroll
                for (int nt = 0; nt < 4; nt++) {
                    uint32_t bfr[2] = { bh[nt >> 1][2 * (nt & 1)], bh[nt >> 1][2 * (nt & 1) + 1] };
                    uint32_t blr[2] = { bl[nt >> 1][2 * (nt & 1)], bl[nt >> 1][2 * (nt & 1) + 1] };
                    mma16816(acc[mt][nt], ah[mt], bfr);
                    mma16816(acc[mt][nt], al[mt], bfr);
                    mma16816(acc[mt][nt], ah[mt], blr);
                }
            }
        }
        __syncthreads();
    }

    #pragma unroll
    for (int mt = 0; mt < 2; mt++) {
        #pragma unroll
        for (int nt = 0; nt < 4; nt++) {
            int mrow = m0 + wm + mt * 16 + (lane >> 2);
            int ncol = n0 + wn + nt * 8 + 2 * (lane & 3);
            float* d = acc[mt][nt];
            if (ncol < N) {
                long o0 = (long)mrow * N + ncol;
                long o1 = (long)(mrow + 8) * N + ncol;
                atomicAdd(&C[o0],     d[0]);
                atomicAdd(&C[o0 + 1], d[1]);
                atomicAdd(&C[o1],     d[2]);
                atomicAdd(&C[o1 + 1], d[3]);
            }
        }
    }
}

// ---------------- fused small kernels ----------------
__global__ void rmsnorm_k(const float* __restrict__ X, const float* __restrict__ w,
                          float* __restrict__ Yf,
                          __nv_bfloat16* __restrict__ Hh, __nv_bfloat16* __restrict__ Hl)
{
    int row = blockIdx.x;
    const float* xr = X + (long)row*DM;
    float s = 0.f;
    for (int c = threadIdx.x; c < DM; c += 256) { float v = xr[c]; s = fmaf(v, v, s); }
    __shared__ float red[256];
    red[threadIdx.x] = s; __syncthreads();
    for (int o = 128; o > 0; o >>= 1) {
        if (threadIdx.x < o) red[threadIdx.x] += red[threadIdx.x + o];
        __syncthreads();
    }
    float scale = rsqrtf(red[0] * (1.0f/DM) + 1e-5f);
    for (int c = threadIdx.x; c < DM; c += 256) {
        float v = xr[c] * scale * w[c];
        if (Yf) Yf[(long)row*DM + c] = v;
        if (Hh) {
            __nv_bfloat16 h, l; split1(v, h, l);
            Hh[(long)row*DM + c] = h;
            Hl[(long)row*DM + c] = l;
        }
    }
}

__global__ void conv_silu_k(const float* __restrict__ xz, const float* __restrict__ cw,
                            const float* __restrict__ cb, float* __restrict__ xc,
                            __nv_bfloat16* __restrict__ Hh, __nv_bfloat16* __restrict__ Hl)
{
    int d   = blockIdx.x*256 + threadIdx.x;
    int row = blockIdx.y;
    int l   = row & (SL-1);
    const float4 w4 = *(const float4*)(cw + d*4);
    float acc = cb[d];
    if (l >= 3) acc = fmaf(xz[(long)(row-3)*2*DI + d], w4.x, acc);
    if (l >= 2) acc = fmaf(xz[(long)(row-2)*2*DI + d], w4.y, acc);
    if (l >= 1) acc = fmaf(xz[(long)(row-1)*2*DI + d], w4.z, acc);
    acc = fmaf(xz[(long)row*2*DI + d], w4.w, acc);
    float sig = 1.f / (1.f + __expf(-acc));
    float v = acc * sig;
    long o = (long)row*DI + d;
    xc[o] = v;
    __nv_bfloat16 h, lo; split1(v, h, lo);
    Hh[o] = h; Hl[o] = lo;
}

__global__ void dt_epi_k(float* __restrict__ dt, const float* __restrict__ dtb,
                         const float* __restrict__ xc, float* __restrict__ u,
                         __nv_bfloat16* __restrict__ Hh, __nv_bfloat16* __restrict__ Hl)
{
    int i = blockIdx.x*256 + threadIdx.x;
    int d = i % DI;
    float x = dt[i] + dtb[d];
    float sp = (x > 20.f) ? x : log1pf(__expf(x));
    dt[i] = sp;
    float uv = sp * xc[i];
    u[i] = uv;
    __nv_bfloat16 h, l; split1(uv, h, l);
    Hh[i] = h; Hl[i] = l;
}

// ---------------- SIMT 64x64 SGEMM (dt_proj: K=48) ----------------
__global__ __launch_bounds__(256) void sgemm_nt(
    const float* __restrict__ A, const float* __restrict__ B,
    float* __restrict__ C,
    int M, int N, int K, int lda, int ldb)
{
    __shared__ float As[16][64];
    __shared__ float Bs[16][64];
    const int tid  = threadIdx.x;
    const int m0   = blockIdx.y*64, n0 = blockIdx.x*64;
    const int lrow = tid >> 2, lc4 = (tid & 3) << 2;
    const int tx   = tid & 15,  ty = tid >> 4;

    float acc[4][4] = {};
    const float* Aptr = A + (long)(m0 + lrow)*lda + lc4;
    const float* Bptr = B + (long)(n0 + lrow)*ldb + lc4;
    const bool bvalid = (n0 + lrow) < N;

    for (int k0 = 0; k0 < K; k0 += 16) {
        float4 av = *(const float4*)(Aptr + k0);
        float4 bvv = make_float4(0.f, 0.f, 0.f, 0.f);
        if (bvalid) bvv = *(const float4*)(Bptr + k0);
        __syncthreads();
        As[lc4+0][lrow]=av.x; As[lc4+1][lrow]=av.y; As[lc4+2][lrow]=av.z; As[lc4+3][lrow]=av.w;
        Bs[lc4+0][lrow]=bvv.x; Bs[lc4+1][lrow]=bvv.y; Bs[lc4+2][lrow]=bvv.z; Bs[lc4+3][lrow]=bvv.w;
        __syncthreads();
        #pragma unroll
        for (int k = 0; k < 16; k++) {
            float4 a = *(const float4*)(&As[k][ty<<2]);
            float4 b = *(const float4*)(&Bs[k][tx<<2]);
            acc[0][0]=fmaf(a.x,b.x,acc[0][0]); acc[0][1]=fmaf(a.x,b.y,acc[0][1]);
            acc[0][2]=fmaf(a.x,b.z,acc[0][2]); acc[0][3]=fmaf(a.x,b.w,acc[0][3]);
            acc[1][0]=fmaf(a.y,b.x,acc[1][0]); acc[1][1]=fmaf(a.y,b.y,acc[1][1]);
            acc[1][2]=fmaf(a.y,b.z,acc[1][2]); acc[1][3]=fmaf(a.y,b.w,acc[1][3]);
            acc[2][0]=fmaf(a.z,b.x,acc[2][0]); acc[2][1]=fmaf(a.z,b.y,acc[2][1]);
            acc[2][2]=fmaf(a.z,b.z,acc[2][2]); acc[2][3]=fmaf(a.z,b.w,acc[2][3]);
            acc[3][0]=fmaf(a.w,b.x,acc[3][0]); acc[3][1]=fmaf(a.w,b.y,acc[3][1]);
            acc[3][2]=fmaf(a.w,b.z,acc[3][2]); acc[3][3]=fmaf(a.w,b.w,acc[3][3]);
        }
    }
    #pragma unroll
    for (int i = 0; i < 4; i++) {
        int m = m0 + (ty<<2) + i;
        #pragma unroll
        for (int j = 0; j < 4; j++) {
            int n = n0 + (tx<<2) + j;
            if (n < N) C[(long)m*N + n] = acc[i][j];
        }
    }
}

// ---------------- w_t = sum_{s<t} beta^{t-1-s} P[s,t] b_s ----------------
__global__ void wk_k(const float* __restrict__ P, const float* __restrict__ xdbl,
                     float* __restrict__ W)
{
    int t = blockIdx.x, b = blockIdx.y, tid = threadIdx.x;
    const float* Prow = P + ((long)b*SL + t)*SL;
    float acc[16];
    #pragma unroll
    for (int n = 0; n < 16; n++) acc[n] = 0.f;

    float decay = exp2f((float)tid * -0.15200309344504995f);
    const float step = 1.3901084526083426e-06f;
    for (int s = t - 1 - tid; s >= 0; s -= 128) {
        float p = Prow[s] * decay;
        const float* bm = xdbl + ((long)b*SL + s)*XD + DR;
        float4 b0 = *(const float4*)(bm);
        float4 b1 = *(const float4*)(bm + 4);
        float4 b2 = *(const float4*)(bm + 8);
        float4 b3 = *(const float4*)(bm + 12);
        acc[0]=fmaf(p,b0.x,acc[0]);  acc[1]=fmaf(p,b0.y,acc[1]);
        acc[2]=fmaf(p,b0.z,acc[2]);  acc[3]=fmaf(p,b0.w,acc[3]);
        acc[4]=fmaf(p,b1.x,acc[4]);  acc[5]=fmaf(p,b1.y,acc[5]);
        acc[6]=fmaf(p,b1.z,acc[6]);  acc[7]=fmaf(p,b1.w,acc[7]);
        acc[8]=fmaf(p,b2.x,acc[8]);  acc[9]=fmaf(p,b2.y,acc[9]);
        acc[10]=fmaf(p,b2.z,acc[10]); acc[11]=fmaf(p,b2.w,acc[11]);
        acc[12]=fmaf(p,b3.x,acc[12]); acc[13]=fmaf(p,b3.y,acc[13]);
        acc[14]=fmaf(p,b3.z,acc[14]); acc[15]=fmaf(p,b3.w,acc[15]);
        decay *= step;
    }
    __shared__ float red[128][17];
    #pragma unroll
    for (int n = 0; n < 16; n++) red[tid][n] = acc[n];
    __syncthreads();
    for (int o = 64; o > 0; o >>= 1) {
        if (tid < o) {
            #pragma unroll
            for (int n = 0; n < 16; n++) red[tid][n] += red[tid+o][n];
        }
        __syncthreads();
    }
    if (tid < 16) W[((long)b*SL + t)*DS + tid] = red[0][tid];
}

// ---------------- G scan (Kogge-Stone over t, decay beta^2) ----------------
__global__ void gscan_k(const float* __restrict__ xdbl, const float* __restrict__ W,
                        const float* __restrict__ P, float* __restrict__ G)
{
    int nm = blockIdx.x;
    int b  = blockIdx.y;
    int n  = nm >> 4, m = nm & 15;
    int t  = threadIdx.x;
    long row = (long)b*SL + t;

    float bn  = xdbl[row*XD + DR + n];
    float bmv = xdbl[row*XD + DR + m];
    float wn  = W[row*DS + n], wm = W[row*DS + m];
    float ptt = P[row*SL + t];
    float g = 0.9f*(bn*wm + wn*bmv) + ptt*bn*bmv;

    __shared__ float sm[SL];
    sm[t] = g; __syncthreads();
    float lam = 0.81f;
    for (int o = 1; o < SL; o <<= 1) {
        float prev = (t >= o) ? sm[t-o] : 0.f;
        __syncthreads();
        g = fmaf(lam, prev, g);
        sm[t] = g;
        __syncthreads();
        lam *= lam;
    }
    G[row*256 + nm] = g;
}

// ---------------- N_t = (aI + b*S + c*S^2)/f ----------------
__global__ void mbuild_k(const float* __restrict__ G, float* __restrict__ Nm)
{
    int bt  = blockIdx.x;
    int tid = threadIdx.x;
    __shared__ float Gs[256], Ss[256];
    __shared__ float fsh;
    Gs[tid] = G[(long)bt*256 + tid];
    __syncthreads();
    if (tid == 0) {
        float tr = 0.f;
        #pragma unroll
        for (int i = 0; i < 16; i++) tr += Gs[i*17];
        fsh = sqrtf(tr) + 1e-7f;
    }
    __syncthreads();
    float f = fsh, fi2 = 1.f/(f*f);
    Ss[tid] = Gs[tid] * fi2;
    __syncthreads();
    int n = tid >> 4, m = tid & 15;
    float s2 = 0.f;
    #pragma unroll
    for (int k = 0; k < 16; k++) s2 = fmaf(Ss[n*16 + k], Ss[k*16 + m], s2);
    float sv = Ss[tid];
    float Mv = fmaf(-4.775f, sv, 2.0315f*s2);
    if (n == m) Mv += 3.4445f;
    Nm[(long)bt*256 + tid] = Mv / f;
}

// ---------------- sequential scan: 256 threads, 32 channels/block ----------
__global__ void __launch_bounds__(256)
scan_k(const float* __restrict__ Nm, const float* __restrict__ xdbl,
       const float* __restrict__ U, const float* __restrict__ DT,
       const float* __restrict__ A_log, const float* __restrict__ xc,
       const float* __restrict__ xz, const float* __restrict__ Dp,
       __nv_bfloat16* __restrict__ Yh, __nv_bfloat16* __restrict__ Yl)
{
    const int b    = blockIdx.y;
    const int tid  = threadIdx.x;            // 256
    const int ch   = blockIdx.x*32 + (tid >> 3);
    const int lane = tid & 7;
    const int n0   = lane*2;

    const float An0 = -__expf(A_log[ch*DS + n0]);
    const float An1 = -__expf(A_log[ch*DS + n0 + 1]);
    const float Dv  = Dp[ch];

    float v0=0.f, v1=0.f, h0=0.f, h1=0.f;
    __shared__ float Ns[2][256];
    __shared__ float bs[2][16], Cs[2][16];
    const float* Nbase = Nm + (long)b*SL*256;
    const long xrow = (long)b*SL*XD + DR;

    // prologue: buf0 = t0, regs = t1
    float4 nv; float bsv = 0.f, csv = 0.f;
    if (tid < 64) {
        *(float4*)&Ns[0][tid*4] = *(const float4*)(Nbase + tid*4);
        nv = *(const float4*)(Nbase + 256 + tid*4);
    } else if (tid < 80) {
        bs[0][tid-64] = xdbl[xrow + (tid-64)];
        bsv = xdbl[xrow + XD + (tid-64)];
    } else if (tid < 96) {
        Cs[0][tid-80] = xdbl[xrow + DS + (tid-80)];
        csv = xdbl[xrow + XD + DS + (tid-80)];
    }
    const long base_di = (long)b*SL*DI + ch;
    const long base_z  = (long)b*SL*2*DI + DI + ch;
    float uCur  = U [base_di],      dtCur = DT[base_di];
    float xcCur = xc[base_di],      zCur  = xz[base_z];
    float uNxt  = U [base_di + DI], dtNxt = DT[base_di + DI];
    float xcNxt = xc[base_di + DI], zNxt  = xz[base_z + 2*DI];
    __syncthreads();

    for (int t = 0; t < SL; t++) {
        const int p = t & 1;
        if (t + 1 < SL) {
            if (tid < 64)       *(float4*)&Ns[p^1][tid*4] = nv;
            else if (tid < 80)  bs[p^1][tid-64] = bsv;
            else if (tid < 96)  Cs[p^1][tid-80] = csv;
        }
        if (t + 2 < SL) {
            if (tid < 64)       nv  = *(const float4*)(Nbase + (long)(t+2)*256 + tid*4);
            else if (tid < 80)  bsv = xdbl[xrow + (long)(t+2)*XD + (tid-64)];
            else if (tid < 96)  csv = xdbl[xrow + (long)(t+2)*XD + DS + (tid-80)];
        }
        const float ut = uCur, dtt = dtCur, xcv = xcCur, zv = zCur;
        uCur = uNxt; dtCur = dtNxt; xcCur = xcNxt; zCur = zNxt;
        if (t + 2 < SL) {
            uNxt  = U [base_di + (long)(t+2)*DI];
            dtNxt = DT[base_di + (long)(t+2)*DI];
            xcNxt = xc[base_di + (long)(t+2)*DI];
            zNxt  = xz[base_z + (long)(t+2)*2*DI];
        }

        v0 = fmaf(0.9f, v0, ut*bs[p][n0]);
        v1 = fmaf(0.9f, v1, ut*bs[p][n0+1]);
        float dA0 = __expf(dtt*An0), dA1 = __expf(dtt*An1);

        float a0e=0.f, a1e=0.f, a0o=0.f, a1o=0.f;
        #pragma unroll
        for (int j = 0; j < 8; j += 2) {
            float vm0 = __shfl_sync(0xffffffffu, v0, j, 8);
            float vm1 = __shfl_sync(0xffffffffu, v1, j, 8);
            float2 r0 = *(const float2*)&Ns[p][(2*j)*16 + n0];
            float2 r1 = *(const float2*)&Ns[p][(2*j+1)*16 + n0];
            a0e = fmaf(vm0, r0.x, a0e); a1e = fmaf(vm0, r0.y, a1e);
            a0e = fmaf(vm1, r1.x, a0e); a1e = fmaf(vm1, r1.y, a1e);
            float wm0 = __shfl_sync(0xffffffffu, v0, j+1, 8);
            float wm1 = __shfl_sync(0xffffffffu, v1, j+1, 8);
            float2 q0 = *(const float2*)&Ns[p][(2*j+2)*16 + n0];
            float2 q1 = *(const float2*)&Ns[p][(2*j+3)*16 + n0];
            a0o = fmaf(wm0, q0.x, a0o); a1o = fmaf(wm0, q0.y, a1o);
            a0o = fmaf(wm1, q1.x, a0o); a1o = fmaf(wm1, q1.y, a1o);
        }
        h0 = fmaf(dA0, h0, a0e + a0o);
        h1 = fmaf(dA1, h1, a1e + a1o);

        float yv = h0*Cs[p][n0] + h1*Cs[p][n0+1];
        yv += __shfl_xor_sync(0xffffffffu, yv, 4, 8);
        yv += __shfl_xor_sync(0xffffffffu, yv, 2, 8);
        yv += __shfl_xor_sync(0xffffffffu, yv, 1, 8);
        if (lane == 0) {
            float sig = 1.f / (1.f + __expf(-zv));
            float yo = (yv + Dv*xcv) * (zv*sig);
            __nv_bfloat16 hh, ll; split1(yo, hh, ll);
            long o = base_di + (long)t*DI;
            Yh[o] = hh; Yl[o] = ll;
        }
        __syncthreads();
    }
}

// ---------------- launcher ----------------
extern "C" void kernel_launch(void* const* d_in, const int* in_sizes, int n_in,
                              void* d_out, int out_size)
{
    const float* x    = (const float*)d_in[0];
    const float* inw  = (const float*)d_in[1];
    const float* cw   = (const float*)d_in[2];
    const float* cb   = (const float*)d_in[3];
    const float* xpw  = (const float*)d_in[4];
    const float* dtw  = (const float*)d_in[5];
    const float* dtb  = (const float*)d_in[6];
    const float* alog = (const float*)d_in[7];
    const float* Dpar = (const float*)d_in[8];
    const float* outw = (const float*)d_in[9];
    const float* nw   = (const float*)d_in[10];
    const float* fnw  = (const float*)d_in[11];
    float* out = (float*)d_out;

    float *xres,*xz,*xc,*xdbl,*dt,*u,*P,*W,*G,*Mm;
    __nv_bfloat16 *Ah,*Al,*Bh,*Bl;
    cudaGetSymbolAddress((void**)&xres, g_xres);
    cudaGetSymbolAddress((void**)&xz,   g_xz);
    cudaGetSymbolAddress((void**)&xc,   g_xc);
    cudaGetSymbolAddress((void**)&xdbl, g_xdbl);
    cudaGetSymbolAddress((void**)&dt,   g_dt);
    cudaGetSymbolAddress((void**)&u,    g_u);
    cudaGetSymbolAddress((void**)&P,    g_P);
    cudaGetSymbolAddress((void**)&W,    g_W);
    cudaGetSymbolAddress((void**)&G,    g_G);
    cudaGetSymbolAddress((void**)&Mm,   g_M);
    cudaGetSymbolAddress((void**)&Ah,   g_Ah);
    cudaGetSymbolAddress((void**)&Al,   g_Al);
    cudaGetSymbolAddress((void**)&Bh,   g_Bh);
    cudaGetSymbolAddress((void**)&Bl,   g_Bl);

    cudaFuncSetAttribute(hgemm_nt, cudaFuncAttributeMaxDynamicSharedMemorySize, HG_SMEM);

    copy_k<<<(BL*DM + 255)/256, 256>>>(x, xres, BL*DM);

    const int nz = BL*2*DI/4 + BL*XD/4 + NB*SL*SL/4;

    for (int layer = 0; layer < 2; layer++) {
        const float* inw_l  = inw  + (long)layer*2*DI*DM;
        const float* cw_l   = cw   + (long)layer*DI*4;
        const float* cb_l   = cb   + (long)layer*DI;
        const float* xpw_l  = xpw  + (long)layer*XD*DI;
        const float* dtw_l  = dtw  + (long)layer*DI*DR;
        const float* dtb_l  = dtb  + (long)layer*DI;
        const float* alog_l = alog + (long)layer*DI*DS;
        const float* Dp_l   = Dpar + (long)layer*DI;
        const float* outw_l = outw + (long)layer*DM*DI;
        const float* nw_l   = nw   + (long)layer*DM;

        rmsnorm_k<<<BL, 256>>>(xres, nw_l, nullptr, Ah, Al);
        split_k<<<(2*DI*DM/4 + 255)/256, 256>>>((const float4*)inw_l, (uint2*)Bh, (uint2*)Bl, 2*DI*DM/4);
        zero3_k<<<(nz + 255)/256, 256>>>((float4*)xz, BL*2*DI/4,
                                         (float4*)xdbl, BL*XD/4,
                                         (float4*)P, NB*SL*SL/4);
        // xz += xn @ in_w^T : M=1024, N=3072, K=768, split-K 2
        hgemm_nt<<<dim3(2*DI/128, BL/128, 2), 512, HG_SMEM>>>(
            Ah, Al, Bh, Bl, xz, BL, 2*DI, 384, DM, DM, 0, 0, 0, 0, 2);

        conv_silu_k<<<dim3(DI/256, BL), 256>>>(xz, cw_l, cb_l, xc, Ah, Al);

        split_k<<<(XD*DI/4 + 255)/256, 256>>>((const float4*)xpw_l, (uint2*)Bh, (uint2*)Bl, XD*DI/4);
        // xdbl += xc @ xp_w^T : M=1024, N=80, K=1536, split-K 6
        hgemm_nt<<<dim3(1, BL/128, 6), 512, HG_SMEM>>>(
            Ah, Al, Bh, Bl, xdbl, BL, XD, 256, DI, DI, 0, 0, 0, 0, 6);

        // dt_pre = dt_lr @ dtp_w^T : M=1024, N=1536, K=48 (SIMT)
        sgemm_nt<<<dim3(DI/64, BL/64), 256>>>(xdbl, dtw_l, dt, BL, DI, DR, XD, DR);

        dt_epi_k<<<BL*DI/256, 256>>>(dt, dtb_l, xc, u, Ah, Al);

        // P += U U^T : M=N=512, K=1536, batched NB, lower-tri, split-K 4
        hgemm_nt<<<dim3(SL/128, SL/128, NB*4), 512, HG_SMEM>>>(
            Ah, Al, Ah, Al, P, SL, SL, 384, DI, DI,
            (long)SL*DI, (long)SL*DI, (long)SL*SL, 2, 4);

        wk_k<<<dim3(SL, NB), 128>>>(P, xdbl, W);
        gscan_k<<<dim3(256, NB), 512>>>(xdbl, W, P, G);
        mbuild_k<<<NB*SL, 256>>>(G, Mm);
        scan_k<<<dim3(DI/32, NB), 256>>>(Mm, xdbl, u, dt, alog_l, xc, xz, Dp_l, Ah, Al);

        split_k<<<(DM*DI/4 + 255)/256, 256>>>((const float4*)outw_l, (uint2*)Bh, (uint2*)Bl, DM*DI/4);
        // xres += y @ out_w^T : M=1024, N=768, K=1536, split-K 3 (residual in place)
        hgemm_nt<<<dim3(DM/128, BL/128, 3), 512, HG_SMEM>>>(
            Ah, Al, Bh, Bl, xres, BL, DM, 512, DI, DI, 0, 0, 0, 0, 3);
    }

    rmsnorm_k<<<BL, 256>>>(xres, fnw, out, nullptr, nullptr);
}

// round 15
// speedup vs baseline: 1.3945x; 1.0369x over previous
#include <cuda_runtime.h>
#include <cuda_bf16.h>
#include <math.h>
#include <stdint.h>

#define NB 2
#define SL 512
#define DM 768
#define DI 1536
#define DS 16
#define XD 80
#define DR 48
#define BL (NB*SL)

// ---------------- scratch ----------------
__device__ float g_xres[BL*DM];
__device__ float g_xz  [BL*2*DI];
__device__ float g_xc  [BL*DI];
__device__ float g_xdbl[BL*XD];
__device__ float g_dt  [BL*DI];
__device__ float g_u   [BL*DI];
__device__ float g_P   [NB*SL*SL];
__device__ float g_W   [NB*SL*DS];
__device__ float g_G   [NB*SL*DS*DS];
__device__ float g_M   [NB*SL*DS*DS];
__device__ __align__(16) __nv_bfloat16 g_Ah[BL*DI];
__device__ __align__(16) __nv_bfloat16 g_Al[BL*DI];
__device__ __align__(16) __nv_bfloat16 g_Bh[2*DI*DM];
__device__ __align__(16) __nv_bfloat16 g_Bl[2*DI*DM];
__device__ __align__(16) __nv_bfloat16 g_xdh[BL*XD];
__device__ __align__(16) __nv_bfloat16 g_xdl[BL*XD];
__device__ __align__(16) __nv_bfloat16 g_dwh[DI*64];
__device__ __align__(16) __nv_bfloat16 g_dwl[DI*64];

// ================= helpers =================
__device__ __forceinline__ uint32_t smem_u32(const void* p) {
    uint32_t a;
    asm("{ .reg .u64 t; cvta.to.shared.u64 t, %1; cvt.u32.u64 %0, t; }" : "=r"(a) : "l"(p));
    return a;
}

__device__ __forceinline__ void split1(float v, __nv_bfloat16& h, __nv_bfloat16& l) {
    h = __float2bfloat16_rn(v);
    l = __float2bfloat16_rn(v - __bfloat162float(h));
}

__device__ __forceinline__ void cvt_split(float4 v, uint2& hi, uint2& lo) {
    __nv_bfloat162 h0 = __floats2bfloat162_rn(v.x, v.y);
    __nv_bfloat162 h1 = __floats2bfloat162_rn(v.z, v.w);
    float rx = v.x - __bfloat162float(__low2bfloat16(h0));
    float ry = v.y - __bfloat162float(__high2bfloat16(h0));
    float rz = v.z - __bfloat162float(__low2bfloat16(h1));
    float rw = v.w - __bfloat162float(__high2bfloat16(h1));
    __nv_bfloat162 l0 = __floats2bfloat162_rn(rx, ry);
    __nv_bfloat162 l1 = __floats2bfloat162_rn(rz, rw);
    hi.x = *(uint32_t*)&h0; hi.y = *(uint32_t*)&h1;
    lo.x = *(uint32_t*)&l0; lo.y = *(uint32_t*)&l1;
}

__global__ void split_k(const float4* __restrict__ src, uint2* __restrict__ hi,
                        uint2* __restrict__ lo, int n4)
{
    int i = blockIdx.x*256 + threadIdx.x;
    if (i < n4) {
        uint2 h, l;
        cvt_split(src[i], h, l);
        hi[i] = h; lo[i] = l;
    }
}

// split dtw (DI x 48) into zero-padded (DI x 64) bf16 hi/lo
__global__ void split_pad_k(const float* __restrict__ src,
                            __nv_bfloat16* __restrict__ hi, __nv_bfloat16* __restrict__ lo)
{
    int i = blockIdx.x*256 + threadIdx.x;   // < DI*64
    int r = i >> 6, c = i & 63;
    float v = (c < DR) ? src[r*DR + c] : 0.f;
    __nv_bfloat16 h, l; split1(v, h, l);
    hi[i] = h; lo[i] = l;
}

__global__ void zero4_k(float4* __restrict__ a, int na,
                        float4* __restrict__ b, int nb,
                        float4* __restrict__ c, int nc,
                        float4* __restrict__ d, int nd)
{
    int i = blockIdx.x*256 + threadIdx.x;
    float4 z = make_float4(0.f, 0.f, 0.f, 0.f);
    if (i < na) a[i] = z;
    else if (i < na + nb) b[i - na] = z;
    else if (i < na + nb + nc) c[i - na - nb] = z;
    else if (i < na + nb + nc + nd) d[i - na - nb - nc] = z;
}

__global__ void copy_k(const float* __restrict__ src, float* __restrict__ dst, int n)
{
    int i = blockIdx.x*blockDim.x + threadIdx.x;
    if (i < n) dst[i] = src[i];
}

__device__ __forceinline__ void ldsm4(uint32_t a, uint32_t& r0, uint32_t& r1,
                                      uint32_t& r2, uint32_t& r3) {
    asm volatile("ldmatrix.sync.aligned.m8n8.x4.shared.b16 {%0,%1,%2,%3}, [%4];"
                 : "=r"(r0), "=r"(r1), "=r"(r2), "=r"(r3) : "r"(a));
}

__device__ __forceinline__ void mma16816(float* c, const uint32_t* a, const uint32_t* b) {
    asm volatile(
        "mma.sync.aligned.m16n8k16.row.col.f32.bf16.bf16.f32 "
        "{%0,%1,%2,%3}, {%4,%5,%6,%7}, {%8,%9}, {%0,%1,%2,%3};"
        : "+f"(c[0]), "+f"(c[1]), "+f"(c[2]), "+f"(c[3])
        : "r"(a[0]), "r"(a[1]), "r"(a[2]), "r"(a[3]), "r"(b[0]), "r"(b[1]));
}

// ================= tensor-core GEMM, split-K, atomic accumulate =================
// (R12 winning version: register-prefetch staging, single-buffered smem)
// C[m,n] += sum_{k in slice} A[m,k]*B[n,k]; A=Ah+Al, B=Bh+Bl (3-term product).
// grid.z = nbatch*nsplit; slice length Ks (multiple of 64).
// mode bit1: triangular skip. C must be pre-initialized (zeros or residual).
#define HG_SMEM (4*128*64*2)   // 64 KB

__global__ __launch_bounds__(512, 1)
void hgemm_nt(const __nv_bfloat16* __restrict__ Ah, const __nv_bfloat16* __restrict__ Al,
              const __nv_bfloat16* __restrict__ Bh, const __nv_bfloat16* __restrict__ Bl,
              float* __restrict__ C,
              int M, int N, int Ks, int lda, int ldb,
              long sA, long sB, long sC, int mode, int nsplit)
{
    extern __shared__ char smraw[];
    const int m0 = blockIdx.y * 128, n0 = blockIdx.x * 128;
    if ((mode & 2) && (n0 > m0)) return;

    const int bz = blockIdx.z / nsplit;
    const int koff = (blockIdx.z % nsplit) * Ks;
    Ah += bz * sA + koff; Al += bz * sA + koff;
    Bh += bz * sB + koff; Bl += bz * sB + koff;
    C  += bz * sC;

    char* const AhP = smraw;
    char* const AlP = smraw + 16384;
    char* const BhP = smraw + 32768;
    char* const BlP = smraw + 49152;
    const uint32_t Ahu = smem_u32(AhP), Alu = Ahu + 16384, Bhu = Ahu + 32768, Blu = Ahu + 49152;

    const int tid = threadIdx.x;
    const int wid = tid >> 5, lane = tid & 31;
    const int wm = (wid & 3) * 32;
    const int wn = (wid >> 2) * 32;

    const int srow = tid >> 2, sseg = tid & 3;
    const __nv_bfloat16* Ahp = Ah + (long)(m0 + srow) * lda + sseg * 16;
    const __nv_bfloat16* Alp = Al + (long)(m0 + srow) * lda + sseg * 16;
    const __nv_bfloat16* Bhp = Bh + (long)(n0 + srow) * ldb + sseg * 16;
    const __nv_bfloat16* Blp = Bl + (long)(n0 + srow) * ldb + sseg * 16;
    const bool bval = (n0 + srow) < N;

    uint32_t soff[2];
    #pragma unroll
    for (int i = 0; i < 2; i++) {
        uint32_t cc = (uint32_t)(sseg * 2 + i);
        soff[i] = (uint32_t)srow * 128 + ((cc ^ (srow & 7)) * 16);
    }

    const int arow_l = lane & 15, acc_l = lane >> 4;
    const int brow_l = (lane & 7) + ((lane >> 4) << 3), bcc_l = (lane >> 3) & 1;

    float acc[2][4][4];
    #pragma unroll
    for (int mt = 0; mt < 2; mt++)
        #pragma unroll
        for (int nt = 0; nt < 4; nt++)
            #pragma unroll
            for (int q = 0; q < 4; q++) acc[mt][nt][q] = 0.f;

    const int nch = Ks / 64;
    const uint4 zero4 = make_uint4(0, 0, 0, 0);
    uint4 rah[2], ral[2], rbh[2], rbl[2];
    #pragma unroll
    for (int i = 0; i < 2; i++) {
        rah[i] = *(const uint4*)(Ahp + i * 8);
        ral[i] = *(const uint4*)(Alp + i * 8);
        rbh[i] = bval ? *(const uint4*)(Bhp + i * 8) : zero4;
        rbl[i] = bval ? *(const uint4*)(Blp + i * 8) : zero4;
    }

    for (int c = 0; c < nch; c++) {
        #pragma unroll
        for (int i = 0; i < 2; i++) {
            *(uint4*)(AhP + soff[i]) = rah[i];
            *(uint4*)(AlP + soff[i]) = ral[i];
            *(uint4*)(BhP + soff[i]) = rbh[i];
            *(uint4*)(BlP + soff[i]) = rbl[i];
        }
        __syncthreads();

        if (c + 1 < nch) {
            const __nv_bfloat16* ahn = Ahp + (c + 1) * 64;
            const __nv_bfloat16* aln = Alp + (c + 1) * 64;
            const __nv_bfloat16* bhn = Bhp + (c + 1) * 64;
            const __nv_bfloat16* bln = Blp + (c + 1) * 64;
            #pragma unroll
            for (int i = 0; i < 2; i++) {
                rah[i] = *(const uint4*)(ahn + i * 8);
                ral[i] = *(const uint4*)(aln + i * 8);
                rbh[i] = bval ? *(const uint4*)(bhn + i * 8) : zero4;
                rbl[i] = bval ? *(const uint4*)(bln + i * 8) : zero4;
            }
        }

        #pragma unroll
        for (int ks = 0; ks < 4; ks++) {
            uint32_t ah[2][4], al[2][4], bh[2][4], bl[2][4];
            #pragma unroll
            for (int mt = 0; mt < 2; mt++) {
                int row = wm + mt * 16 + arow_l;
                uint32_t cc = (uint32_t)(2 * ks + acc_l);
                uint32_t off = (uint32_t)row * 128 + ((cc ^ (row & 7)) * 16);
                ldsm4(Ahu + off, ah[mt][0], ah[mt][1], ah[mt][2], ah[mt][3]);
                ldsm4(Alu + off, al[mt][0], al[mt][1], al[mt][2], al[mt][3]);
            }
            #pragma unroll
            for (int p = 0; p < 2; p++) {
                int row = wn + p * 16 + brow_l;
                uint32_t cc = (uint32_t)(2 * ks + bcc_l);
                uint32_t off = (uint32_t)row * 128 + ((cc ^ (row & 7)) * 16);
                ldsm4(Bhu + off, bh[p][0], bh[p][1], bh[p][2], bh[p][3]);
                ldsm4(Blu + off, bl[p][0], bl[p][1], bl[p][2], bl[p][3]);
            }
            #pragma unroll
            for (int mt = 0; mt < 2; mt++) {
                #pragma unroll
                for (int nt = 0; nt < 4; nt++) {
                    uint32_t bfr[2] = { bh[nt >> 1][2 * (nt & 1)], bh[nt >> 1][2 * (nt & 1) + 1] };
                    uint32_t blr[2] = { bl[nt >> 1][2 * (nt & 1)], bl[nt >> 1][2 * (nt & 1) + 1] };
                    mma16816(acc[mt][nt], ah[mt], bfr);
                    mma16816(acc[mt][nt], al[mt], bfr);
                    mma16816(acc[mt][nt], ah[mt], blr);
                }
            }
        }
        __syncthreads();
    }

    #pragma unroll
    for (int mt = 0; mt < 2; mt++) {
        #pragma unroll
        for (int nt = 0; nt < 4; nt++) {
            int mrow = m0 + wm + mt * 16 + (lane >> 2);
            int ncol = n0 + wn + nt * 8 + 2 * (lane & 3);
            float* d = acc[mt][nt];
            if (ncol < N) {
                long o0 = (long)mrow * N + ncol;
                long o1 = (long)(mrow + 8) * N + ncol;
                atomicAdd(&C[o0],     d[0]);
                atomicAdd(&C[o0 + 1], d[1]);
                atomicAdd(&C[o1],     d[2]);
                atomicAdd(&C[o1 + 1], d[3]);
            }
        }
    }
}

// ---------------- fused small kernels ----------------
__global__ void rmsnorm_k(const float* __restrict__ X, const float* __restrict__ w,
                          float* __restrict__ Yf,
                          __nv_bfloat16* __restrict__ Hh, __nv_bfloat16* __restrict__ Hl)
{
    int row = blockIdx.x;
    const float* xr = X + (long)row*DM;
    float s = 0.f;
    for (int c = threadIdx.x; c < DM; c += 256) { float v = xr[c]; s = fmaf(v, v, s); }
    __shared__ float red[256];
    red[threadIdx.x] = s; __syncthreads();
    for (int o = 128; o > 0; o >>= 1) {
        if (threadIdx.x < o) red[threadIdx.x] += red[threadIdx.x + o];
        __syncthreads();
    }
    float scale = rsqrtf(red[0] * (1.0f/DM) + 1e-5f);
    for (int c = threadIdx.x; c < DM; c += 256) {
        float v = xr[c] * scale * w[c];
        if (Yf) Yf[(long)row*DM + c] = v;
        if (Hh) {
            __nv_bfloat16 h, l; split1(v, h, l);
            Hh[(long)row*DM + c] = h;
            Hl[(long)row*DM + c] = l;
        }
    }
}

__global__ void conv_silu_k(const float* __restrict__ xz, const float* __restrict__ cw,
                            const float* __restrict__ cb, float* __restrict__ xc,
                            __nv_bfloat16* __restrict__ Hh, __nv_bfloat16* __restrict__ Hl)
{
    int d   = blockIdx.x*256 + threadIdx.x;
    int row = blockIdx.y;
    int l   = row & (SL-1);
    const float4 w4 = *(const float4*)(cw + d*4);
    float acc = cb[d];
    if (l >= 3) acc = fmaf(xz[(long)(row-3)*2*DI + d], w4.x, acc);
    if (l >= 2) acc = fmaf(xz[(long)(row-2)*2*DI + d], w4.y, acc);
    if (l >= 1) acc = fmaf(xz[(long)(row-1)*2*DI + d], w4.z, acc);
    acc = fmaf(xz[(long)row*2*DI + d], w4.w, acc);
    float sig = 1.f / (1.f + __expf(-acc));
    float v = acc * sig;
    long o = (long)row*DI + d;
    xc[o] = v;
    __nv_bfloat16 h, lo; split1(v, h, lo);
    Hh[o] = h; Hl[o] = lo;
}

__global__ void dt_epi_k(float* __restrict__ dt, const float* __restrict__ dtb,
                         const float* __restrict__ xc, float* __restrict__ u,
                         __nv_bfloat16* __restrict__ Hh, __nv_bfloat16* __restrict__ Hl)
{
    int i = blockIdx.x*256 + threadIdx.x;
    int d = i % DI;
    float x = dt[i] + dtb[d];
    float sp = (x > 20.f) ? x : log1pf(__expf(x));
    dt[i] = sp;
    float uv = sp * xc[i];
    u[i] = uv;
    __nv_bfloat16 h, l; split1(uv, h, l);
    Hh[i] = h; Hl[i] = l;
}

// ---------------- w_t = sum_{s<t} beta^{t-1-s} P[s,t] b_s ----------------
__global__ void wk_k(const float* __restrict__ P, const float* __restrict__ xdbl,
                     float* __restrict__ W)
{
    int t = blockIdx.x, b = blockIdx.y, tid = threadIdx.x;
    const float* Prow = P + ((long)b*SL + t)*SL;
    float acc[16];
    #pragma unroll
    for (int n = 0; n < 16; n++) acc[n] = 0.f;

    float decay = exp2f((float)tid * -0.15200309344504995f);
    const float step = 1.3901084526083426e-06f;
    for (int s = t - 1 - tid; s >= 0; s -= 128) {
        float p = Prow[s] * decay;
        const float* bm = xdbl + ((long)b*SL + s)*XD + DR;
        float4 b0 = *(const float4*)(bm);
        float4 b1 = *(const float4*)(bm + 4);
        float4 b2 = *(const float4*)(bm + 8);
        float4 b3 = *(const float4*)(bm + 12);
        acc[0]=fmaf(p,b0.x,acc[0]);  acc[1]=fmaf(p,b0.y,acc[1]);
        acc[2]=fmaf(p,b0.z,acc[2]);  acc[3]=fmaf(p,b0.w,acc[3]);
        acc[4]=fmaf(p,b1.x,acc[4]);  acc[5]=fmaf(p,b1.y,acc[5]);
        acc[6]=fmaf(p,b1.z,acc[6]);  acc[7]=fmaf(p,b1.w,acc[7]);
        acc[8]=fmaf(p,b2.x,acc[8]);  acc[9]=fmaf(p,b2.y,acc[9]);
        acc[10]=fmaf(p,b2.z,acc[10]); acc[11]=fmaf(p,b2.w,acc[11]);
        acc[12]=fmaf(p,b3.x,acc[12]); acc[13]=fmaf(p,b3.y,acc[13]);
        acc[14]=fmaf(p,b3.z,acc[14]); acc[15]=fmaf(p,b3.w,acc[15]);
        decay *= step;
    }
    __shared__ float red[128][17];
    #pragma unroll
    for (int n = 0; n < 16; n++) red[tid][n] = acc[n];
    __syncthreads();
    for (int o = 64; o > 0; o >>= 1) {
        if (tid < o) {
            #pragma unroll
            for (int n = 0; n < 16; n++) red[tid][n] += red[tid+o][n];
        }
        __syncthreads();
    }
    if (tid < 16) W[((long)b*SL + t)*DS + tid] = red[0][tid];
}

// ---------------- G scan (Kogge-Stone over t, decay beta^2) ----------------
__global__ void gscan_k(const float* __restrict__ xdbl, const float* __restrict__ W,
                        const float* __restrict__ P, float* __restrict__ G)
{
    int nm = blockIdx.x;
    int b  = blockIdx.y;
    int n  = nm >> 4, m = nm & 15;
    int t  = threadIdx.x;
    long row = (long)b*SL + t;

    float bn  = xdbl[row*XD + DR + n];
    float bmv = xdbl[row*XD + DR + m];
    float wn  = W[row*DS + n], wm = W[row*DS + m];
    float ptt = P[row*SL + t];
    float g = 0.9f*(bn*wm + wn*bmv) + ptt*bn*bmv;

    __shared__ float sm[SL];
    sm[t] = g; __syncthreads();
    float lam = 0.81f;
    for (int o = 1; o < SL; o <<= 1) {
        float prev = (t >= o) ? sm[t-o] : 0.f;
        __syncthreads();
        g = fmaf(lam, prev, g);
        sm[t] = g;
        __syncthreads();
        lam *= lam;
    }
    G[row*256 + nm] = g;
}

// ---------------- N_t = (aI + b*S + c*S^2)/f ----------------
__global__ void mbuild_k(const float* __restrict__ G, float* __restrict__ Nm)
{
    int bt  = blockIdx.x;
    int tid = threadIdx.x;
    __shared__ float Gs[256], Ss[256];
    __shared__ float fsh;
    Gs[tid] = G[(long)bt*256 + tid];
    __syncthreads();
    if (tid == 0) {
        float tr = 0.f;
        #pragma unroll
        for (int i = 0; i < 16; i++) tr += Gs[i*17];
        fsh = sqrtf(tr) + 1e-7f;
    }
    __syncthreads();
    float f = fsh, fi2 = 1.f/(f*f);
    Ss[tid] = Gs[tid] * fi2;
    __syncthreads();
    int n = tid >> 4, m = tid & 15;
    float s2 = 0.f;
    #pragma unroll
    for (int k = 0; k < 16; k++) s2 = fmaf(Ss[n*16 + k], Ss[k*16 + m], s2);
    float sv = Ss[tid];
    float Mv = fmaf(-4.775f, sv, 2.0315f*s2);
    if (n == m) Mv += 3.4445f;
    Nm[(long)bt*256 + tid] = Mv / f;
}

// ---------------- sequential scan (R12 version: 128 thr, 16 ch/block) --------
__global__ void scan_k(const float* __restrict__ Nm, const float* __restrict__ xdbl,
                       const float* __restrict__ U, const float* __restrict__ DT,
                       const float* __restrict__ A_log, const float* __restrict__ xc,
                       const float* __restrict__ xz, const float* __restrict__ Dp,
                       __nv_bfloat16* __restrict__ Yh, __nv_bfloat16* __restrict__ Yl)
{
    const int b    = blockIdx.y;
    const int tid  = threadIdx.x;            // 128
    const int ch   = blockIdx.x*16 + (tid >> 3);
    const int lane = tid & 7;
    const int n0   = lane*2;

    const float An0 = -__expf(A_log[ch*DS + n0]);
    const float An1 = -__expf(A_log[ch*DS + n0 + 1]);
    const float Dv  = Dp[ch];

    float v0=0.f, v1=0.f, h0=0.f, h1=0.f;
    __shared__ float Ns[2][256];
    __shared__ float bs[2][16], Cs[2][16];
    const float* Nbase = Nm + (long)b*SL*256;
    const long xrow = (long)b*SL*XD + DR;

    float4 nv; float bsv = 0.f, csv = 0.f;
    if (tid < 64) {
        *(float4*)&Ns[0][tid*4] = *(const float4*)(Nbase + tid*4);
        nv = *(const float4*)(Nbase + 256 + tid*4);
    } else if (tid < 80) {
        bs[0][tid-64] = xdbl[xrow + (tid-64)];
        bsv = xdbl[xrow + XD + (tid-64)];
    } else if (tid < 96) {
        Cs[0][tid-80] = xdbl[xrow + DS + (tid-80)];
        csv = xdbl[xrow + XD + DS + (tid-80)];
    }
    const long base_di = (long)b*SL*DI + ch;
    const long base_z  = (long)b*SL*2*DI + DI + ch;
    float uCur  = U [base_di],      dtCur = DT[base_di];
    float xcCur = xc[base_di],      zCur  = xz[base_z];
    float uNxt  = U [base_di + DI], dtNxt = DT[base_di + DI];
    float xcNxt = xc[base_di + DI], zNxt  = xz[base_z + 2*DI];
    __syncthreads();

    for (int t = 0; t < SL; t++) {
        const int p = t & 1;
        if (t + 1 < SL) {
            if (tid < 64)       *(float4*)&Ns[p^1][tid*4] = nv;
            else if (tid < 80)  bs[p^1][tid-64] = bsv;
            else if (tid < 96)  Cs[p^1][tid-80] = csv;
        }
        if (t + 2 < SL) {
            if (tid < 64)       nv  = *(const float4*)(Nbase + (long)(t+2)*256 + tid*4);
            else if (tid < 80)  bsv = xdbl[xrow + (long)(t+2)*XD + (tid-64)];
            else if (tid < 96)  csv = xdbl[xrow + (long)(t+2)*XD + DS + (tid-80)];
        }
        const float ut = uCur, dtt = dtCur, xcv = xcCur, zv = zCur;
        uCur = uNxt; dtCur = dtNxt; xcCur = xcNxt; zCur = zNxt;
        if (t + 2 < SL) {
            uNxt  = U [base_di + (long)(t+2)*DI];
            dtNxt = DT[base_di + (long)(t+2)*DI];
            xcNxt = xc[base_di + (long)(t+2)*DI];
            zNxt  = xz[base_z + (long)(t+2)*2*DI];
        }

        v0 = fmaf(0.9f, v0, ut*bs[p][n0]);
        v1 = fmaf(0.9f, v1, ut*bs[p][n0+1]);

        float a0 = 0.f, a1 = 0.f;
        #pragma unroll
        for (int j = 0; j < 8; j++) {
            float vm0 = __shfl_sync(0xffffffffu, v0, j, 8);
            float vm1 = __shfl_sync(0xffffffffu, v1, j, 8);
            float2 r0 = *(const float2*)&Ns[p][(2*j)*16 + n0];
            float2 r1 = *(const float2*)&Ns[p][(2*j+1)*16 + n0];
            a0 = fmaf(vm0, r0.x, a0); a1 = fmaf(vm0, r0.y, a1);
            a0 = fmaf(vm1, r1.x, a0); a1 = fmaf(vm1, r1.y, a1);
        }
        float dA0 = __expf(dtt*An0), dA1 = __expf(dtt*An1);
        h0 = fmaf(dA0, h0, a0);
        h1 = fmaf(dA1, h1, a1);

        float yl = h0*Cs[p][n0] + h1*Cs[p][n0+1];
        yl += __shfl_xor_sync(0xffffffffu, yl, 4, 8);
        yl += __shfl_xor_sync(0xffffffffu, yl, 2, 8);
        yl += __shfl_xor_sync(0xffffffffu, yl, 1, 8);
        if (lane == 0) {
            float sig = 1.f / (1.f + __expf(-zv));
            float yv = (yl + Dv*xcv) * (zv*sig);
            __nv_bfloat16 hh, ll; split1(yv, hh, ll);
            long o = base_di + (long)t*DI;
            Yh[o] = hh; Yl[o] = ll;
        }
        __syncthreads();
    }
}

// ---------------- launcher ----------------
extern "C" void kernel_launch(void* const* d_in, const int* in_sizes, int n_in,
                              void* d_out, int out_size)
{
    const float* x    = (const float*)d_in[0];
    const float* inw  = (const float*)d_in[1];
    const float* cw   = (const float*)d_in[2];
    const float* cb   = (const float*)d_in[3];
    const float* xpw  = (const float*)d_in[4];
    const float* dtw  = (const float*)d_in[5];
    const float* dtb  = (const float*)d_in[6];
    const float* alog = (const float*)d_in[7];
    const float* Dpar = (const float*)d_in[8];
    const float* outw = (const float*)d_in[9];
    const float* nw   = (const float*)d_in[10];
    const float* fnw  = (const float*)d_in[11];
    float* out = (float*)d_out;

    float *xres,*xz,*xc,*xdbl,*dt,*u,*P,*W,*G,*Mm;
    __nv_bfloat16 *Ah,*Al,*Bh,*Bl,*xdh,*xdl,*dwh,*dwl;
    cudaGetSymbolAddress((void**)&xres, g_xres);
    cudaGetSymbolAddress((void**)&xz,   g_xz);
    cudaGetSymbolAddress((void**)&xc,   g_xc);
    cudaGetSymbolAddress((void**)&xdbl, g_xdbl);
    cudaGetSymbolAddress((void**)&dt,   g_dt);
    cudaGetSymbolAddress((void**)&u,    g_u);
    cudaGetSymbolAddress((void**)&P,    g_P);
    cudaGetSymbolAddress((void**)&W,    g_W);
    cudaGetSymbolAddress((void**)&G,    g_G);
    cudaGetSymbolAddress((void**)&Mm,   g_M);
    cudaGetSymbolAddress((void**)&Ah,   g_Ah);
    cudaGetSymbolAddress((void**)&Al,   g_Al);
    cudaGetSymbolAddress((void**)&Bh,   g_Bh);
    cudaGetSymbolAddress((void**)&Bl,   g_Bl);
    cudaGetSymbolAddress((void**)&xdh,  g_xdh);
    cudaGetSymbolAddress((void**)&xdl,  g_xdl);
    cudaGetSymbolAddress((void**)&dwh,  g_dwh);
    cudaGetSymbolAddress((void**)&dwl,  g_dwl);

    cudaFuncSetAttribute(hgemm_nt, cudaFuncAttributeMaxDynamicSharedMemorySize, HG_SMEM);

    copy_k<<<(BL*DM + 255)/256, 256>>>(x, xres, BL*DM);

    const int nz = BL*2*DI/4 + BL*XD/4 + NB*SL*SL/4 + BL*DI/4;

    for (int layer = 0; layer < 2; layer++) {
        const float* inw_l  = inw  + (long)layer*2*DI*DM;
        const float* cw_l   = cw   + (long)layer*DI*4;
        const float* cb_l   = cb   + (long)layer*DI;
        const float* xpw_l  = xpw  + (long)layer*XD*DI;
        const float* dtw_l  = dtw  + (long)layer*DI*DR;
        const float* dtb_l  = dtb  + (long)layer*DI;
        const float* alog_l = alog + (long)layer*DI*DS;
        const float* Dp_l   = Dpar + (long)layer*DI;
        const float* outw_l = outw + (long)layer*DM*DI;
        const float* nw_l   = nw   + (long)layer*DM;

        rmsnorm_k<<<BL, 256>>>(xres, nw_l, nullptr, Ah, Al);
        split_k<<<(2*DI*DM/4 + 255)/256, 256>>>((const float4*)inw_l, (uint2*)Bh, (uint2*)Bl, 2*DI*DM/4);
        zero4_k<<<(nz + 255)/256, 256>>>((float4*)xz, BL*2*DI/4,
                                         (float4*)xdbl, BL*XD/4,
                                         (float4*)P, NB*SL*SL/4,
                                         (float4*)dt, BL*DI/4);
        // xz += xn @ in_w^T : M=1024, N=3072, K=768, split-K 2
        hgemm_nt<<<dim3(2*DI/128, BL/128, 2), 512, HG_SMEM>>>(
            Ah, Al, Bh, Bl, xz, BL, 2*DI, 384, DM, DM, 0, 0, 0, 0, 2);

        conv_silu_k<<<dim3(DI/256, BL), 256>>>(xz, cw_l, cb_l, xc, Ah, Al);

        split_k<<<(XD*DI/4 + 255)/256, 256>>>((const float4*)xpw_l, (uint2*)Bh, (uint2*)Bl, XD*DI/4);
        // xdbl += xc @ xp_w^T : M=1024, N=80, K=1536, split-K 6
        hgemm_nt<<<dim3(1, BL/128, 6), 512, HG_SMEM>>>(
            Ah, Al, Bh, Bl, xdbl, BL, XD, 256, DI, DI, 0, 0, 0, 0, 6);

        // dt = dt_lr @ dtp_w^T : M=1024, N=1536, K=48 padded to 64 (tensor)
        split_k<<<(BL*XD/4 + 255)/256, 256>>>((const float4*)xdbl, (uint2*)xdh, (uint2*)xdl, BL*XD/4);
        split_pad_k<<<(DI*64 + 255)/256, 256>>>(dtw_l, dwh, dwl);
        hgemm_nt<<<dim3(DI/128, BL/128, 1), 512, HG_SMEM>>>(
            xdh, xdl, dwh, dwl, dt, BL, DI, 64, XD, 64, 0, 0, 0, 0, 1);

        dt_epi_k<<<BL*DI/256, 256>>>(dt, dtb_l, xc, u, Ah, Al);

        // P += U U^T : M=N=512, K=1536, batched NB, lower-tri, split-K 4
        hgemm_nt<<<dim3(SL/128, SL/128, NB*4), 512, HG_SMEM>>>(
            Ah, Al, Ah, Al, P, SL, SL, 384, DI, DI,
            (long)SL*DI, (long)SL*DI, (long)SL*SL, 2, 4);

        wk_k<<<dim3(SL, NB), 128>>>(P, xdbl, W);
        gscan_k<<<dim3(256, NB), 512>>>(xdbl, W, P, G);
        mbuild_k<<<NB*SL, 256>>>(G, Mm);
        scan_k<<<dim3(DI/16, NB), 128>>>(Mm, xdbl, u, dt, alog_l, xc, xz, Dp_l, Ah, Al);

        split_k<<<(DM*DI/4 + 255)/256, 256>>>((const float4*)outw_l, (uint2*)Bh, (uint2*)Bl, DM*DI/4);
        // xres += y @ out_w^T : M=1024, N=768, K=1536, split-K 3 (residual in place)
        hgemm_nt<<<dim3(DM/128, BL/128, 3), 512, HG_SMEM>>>(
            Ah, Al, Bh, Bl, xres, BL, DM, 512, DI, DI, 0, 0, 0, 0, 3);
    }

    rmsnorm_k<<<BL, 256>>>(xres, fnw, out, nullptr, nullptr);
}

// round 16
// speedup vs baseline: 1.4139x; 1.0139x over previous
#include <cuda_runtime.h>
#include <cuda_bf16.h>
#include <math.h>
#include <stdint.h>

#define NB 2
#define SL 512
#define DM 768
#define DI 1536
#define DS 16
#define XD 80
#define DR 48
#define BL (NB*SL)

// ---------------- scratch ----------------
__device__ float g_xres[BL*DM];
__device__ float g_xz  [BL*2*DI];
__device__ float g_xc  [BL*DI];
__device__ float g_xdbl[BL*XD];
__device__ float g_dt  [BL*DI];
__device__ float g_u   [BL*DI];
__device__ float g_P   [NB*SL*SL];
__device__ float g_W   [NB*SL*DS];
__device__ float g_G   [NB*SL*DS*DS];
__device__ float g_M   [NB*SL*DS*DS];
__device__ __align__(16) __nv_bfloat16 g_Ah[BL*DI];
__device__ __align__(16) __nv_bfloat16 g_Al[BL*DI];
__device__ __align__(16) __nv_bfloat16 g_Bh[2*DI*DM];
__device__ __align__(16) __nv_bfloat16 g_Bl[2*DI*DM];
__device__ __align__(16) __nv_bfloat16 g_xdh[BL*XD];
__device__ __align__(16) __nv_bfloat16 g_xdl[BL*XD];
__device__ __align__(16) __nv_bfloat16 g_dwh[DI*64];
__device__ __align__(16) __nv_bfloat16 g_dwl[DI*64];

// ================= helpers =================
__device__ __forceinline__ uint32_t smem_u32(const void* p) {
    uint32_t a;
    asm("{ .reg .u64 t; cvta.to.shared.u64 t, %1; cvt.u32.u64 %0, t; }" : "=r"(a) : "l"(p));
    return a;
}

__device__ __forceinline__ void split1(float v, __nv_bfloat16& h, __nv_bfloat16& l) {
    h = __float2bfloat16_rn(v);
    l = __float2bfloat16_rn(v - __bfloat162float(h));
}

__device__ __forceinline__ void cvt_split(float4 v, uint2& hi, uint2& lo) {
    __nv_bfloat162 h0 = __floats2bfloat162_rn(v.x, v.y);
    __nv_bfloat162 h1 = __floats2bfloat162_rn(v.z, v.w);
    float rx = v.x - __bfloat162float(__low2bfloat16(h0));
    float ry = v.y - __bfloat162float(__high2bfloat16(h0));
    float rz = v.z - __bfloat162float(__low2bfloat16(h1));
    float rw = v.w - __bfloat162float(__high2bfloat16(h1));
    __nv_bfloat162 l0 = __floats2bfloat162_rn(rx, ry);
    __nv_bfloat162 l1 = __floats2bfloat162_rn(rz, rw);
    hi.x = *(uint32_t*)&h0; hi.y = *(uint32_t*)&h1;
    lo.x = *(uint32_t*)&l0; lo.y = *(uint32_t*)&l1;
}

__global__ void split_k(const float4* __restrict__ src, uint2* __restrict__ hi,
                        uint2* __restrict__ lo, int n4)
{
    int i = blockIdx.x*256 + threadIdx.x;
    if (i < n4) {
        uint2 h, l;
        cvt_split(src[i], h, l);
        hi[i] = h; lo[i] = l;
    }
}

// split dtw (DI x 48) into zero-padded (DI x 64) bf16 hi/lo
__global__ void split_pad_k(const float* __restrict__ src,
                            __nv_bfloat16* __restrict__ hi, __nv_bfloat16* __restrict__ lo)
{
    int i = blockIdx.x*256 + threadIdx.x;   // < DI*64
    int r = i >> 6, c = i & 63;
    float v = (c < DR) ? src[r*DR + c] : 0.f;
    __nv_bfloat16 h, l; split1(v, h, l);
    hi[i] = h; lo[i] = l;
}

__global__ void zero3_k(float4* __restrict__ a, int na,
                        float4* __restrict__ b, int nb,
                        float4* __restrict__ c, int nc)
{
    int i = blockIdx.x*256 + threadIdx.x;
    float4 z = make_float4(0.f, 0.f, 0.f, 0.f);
    if (i < na) a[i] = z;
    else if (i < na + nb) b[i - na] = z;
    else if (i < na + nb + nc) c[i - na - nb] = z;
}

__global__ void copy_k(const float* __restrict__ src, float* __restrict__ dst, int n)
{
    int i = blockIdx.x*blockDim.x + threadIdx.x;
    if (i < n) dst[i] = src[i];
}

__device__ __forceinline__ void ldsm4(uint32_t a, uint32_t& r0, uint32_t& r1,
                                      uint32_t& r2, uint32_t& r3) {
    asm volatile("ldmatrix.sync.aligned.m8n8.x4.shared.b16 {%0,%1,%2,%3}, [%4];"
                 : "=r"(r0), "=r"(r1), "=r"(r2), "=r"(r3) : "r"(a));
}

__device__ __forceinline__ void mma16816(float* c, const uint32_t* a, const uint32_t* b) {
    asm volatile(
        "mma.sync.aligned.m16n8k16.row.col.f32.bf16.bf16.f32 "
        "{%0,%1,%2,%3}, {%4,%5,%6,%7}, {%8,%9}, {%0,%1,%2,%3};"
        : "+f"(c[0]), "+f"(c[1]), "+f"(c[2]), "+f"(c[3])
        : "r"(a[0]), "r"(a[1]), "r"(a[2]), "r"(a[3]), "r"(b[0]), "r"(b[1]));
}

// ================= tensor-core GEMM, split-K, atomic accumulate =================
// DOUBLE-BUFFERED smem (2 stages x 64KB), ONE barrier per K-chunk.
// C[m,n] += sum_{k in slice} A[m,k]*B[n,k]; A=Ah+Al, B=Bh+Bl (3-term product).
// grid.z = nbatch*nsplit; slice length Ks (multiple of 64).
// mode bit1: triangular skip. mode bit2: plain store (single writer) instead of atomicAdd.
#define HG_SMEM (2*4*128*64*2)   // 128 KB

__global__ __launch_bounds__(512, 1)
void hgemm_nt(const __nv_bfloat16* __restrict__ Ah, const __nv_bfloat16* __restrict__ Al,
              const __nv_bfloat16* __restrict__ Bh, const __nv_bfloat16* __restrict__ Bl,
              float* __restrict__ C,
              int M, int N, int Ks, int lda, int ldb,
              long sA, long sB, long sC, int mode, int nsplit)
{
    extern __shared__ char smraw[];
    const int m0 = blockIdx.y * 128, n0 = blockIdx.x * 128;
    if ((mode & 2) && (n0 > m0)) return;

    const int bz = blockIdx.z / nsplit;
    const int koff = (blockIdx.z % nsplit) * Ks;
    Ah += bz * sA + koff; Al += bz * sA + koff;
    Bh += bz * sB + koff; Bl += bz * sB + koff;
    C  += bz * sC;

    const uint32_t sb = smem_u32(smraw);

    const int tid = threadIdx.x;
    const int wid = tid >> 5, lane = tid & 31;
    const int wm = (wid & 3) * 32;
    const int wn = (wid >> 2) * 32;

    const int srow = tid >> 2, sseg = tid & 3;
    const __nv_bfloat16* Ahp = Ah + (long)(m0 + srow) * lda + sseg * 16;
    const __nv_bfloat16* Alp = Al + (long)(m0 + srow) * lda + sseg * 16;
    const __nv_bfloat16* Bhp = Bh + (long)(n0 + srow) * ldb + sseg * 16;
    const __nv_bfloat16* Blp = Bl + (long)(n0 + srow) * ldb + sseg * 16;
    const bool bval = (n0 + srow) < N;

    uint32_t soff[2];
    #pragma unroll
    for (int i = 0; i < 2; i++) {
        uint32_t cc = (uint32_t)(sseg * 2 + i);
        soff[i] = (uint32_t)srow * 128 + ((cc ^ (srow & 7)) * 16);
    }

    const int arow_l = lane & 15, acc_l = lane >> 4;
    const int brow_l = (lane & 7) + ((lane >> 4) << 3), bcc_l = (lane >> 3) & 1;

    float acc[2][4][4];
    #pragma unroll
    for (int mt = 0; mt < 2; mt++)
        #pragma unroll
        for (int nt = 0; nt < 4; nt++)
            #pragma unroll
            for (int q = 0; q < 4; q++) acc[mt][nt][q] = 0.f;

    const int nch = Ks / 64;
    const uint4 zero4 = make_uint4(0, 0, 0, 0);
    uint4 rah[2], ral[2], rbh[2], rbl[2];

    // load chunk 0
    #pragma unroll
    for (int i = 0; i < 2; i++) {
        rah[i] = *(const uint4*)(Ahp + i * 8);
        ral[i] = *(const uint4*)(Alp + i * 8);
        rbh[i] = bval ? *(const uint4*)(Bhp + i * 8) : zero4;
        rbl[i] = bval ? *(const uint4*)(Blp + i * 8) : zero4;
    }
    // store chunk 0 into stage 0
    {
        char* const st = smraw;
        #pragma unroll
        for (int i = 0; i < 2; i++) {
            *(uint4*)(st + soff[i])         = rah[i];
            *(uint4*)(st + 16384 + soff[i]) = ral[i];
            *(uint4*)(st + 32768 + soff[i]) = rbh[i];
            *(uint4*)(st + 49152 + soff[i]) = rbl[i];
        }
    }
    // prefetch chunk 1
    if (nch > 1) {
        #pragma unroll
        for (int i = 0; i < 2; i++) {
            rah[i] = *(const uint4*)(Ahp + 64 + i * 8);
            ral[i] = *(const uint4*)(Alp + 64 + i * 8);
            rbh[i] = bval ? *(const uint4*)(Bhp + 64 + i * 8) : zero4;
            rbl[i] = bval ? *(const uint4*)(Blp + 64 + i * 8) : zero4;
        }
    }
    __syncthreads();

    for (int c = 0; c < nch; c++) {
        const int s = c & 1;
        const uint32_t Ahu = sb + (uint32_t)s * 65536;
        const uint32_t Alu = Ahu + 16384, Bhu = Ahu + 32768, Blu = Ahu + 49152;

        // MMA phase on stage s
        #pragma unroll
        for (int ks = 0; ks < 4; ks++) {
            uint32_t ah[2][4], al[2][4], bh[2][4], bl[2][4];
            #pragma unroll
            for (int mt = 0; mt < 2; mt++) {
                int row = wm + mt * 16 + arow_l;
                uint32_t cc = (uint32_t)(2 * ks + acc_l);
                uint32_t off = (uint32_t)row * 128 + ((cc ^ (row & 7)) * 16);
                ldsm4(Ahu + off, ah[mt][0], ah[mt][1], ah[mt][2], ah[mt][3]);
                ldsm4(Alu + off, al[mt][0], al[mt][1], al[mt][2], al[mt][3]);
            }
            #pragma unroll
            for (int p = 0; p < 2; p++) {
                int row = wn + p * 16 + brow_l;
                uint32_t cc = (uint32_t)(2 * ks + bcc_l);
                uint32_t off = (uint32_t)row * 128 + ((cc ^ (row & 7)) * 16);
                ldsm4(Bhu + off, bh[p][0], bh[p][1], bh[p][2], bh[p][3]);
                ldsm4(Blu + off, bl[p][0], bl[p][1], bl[p][2], bl[p][3]);
            }
            #pragma unroll
            for (int mt = 0; mt < 2; mt++) {
                #pragma unroll
                for (int nt = 0; nt < 4; nt++) {
                    uint32_t bfr[2] = { bh[nt >> 1][2 * (nt & 1)], bh[nt >> 1][2 * (nt & 1) + 1] };
                    uint32_t blr[2] = { bl[nt >> 1][2 * (nt & 1)], bl[nt >> 1][2 * (nt & 1) + 1] };
                    mma16816(acc[mt][nt], ah[mt], bfr);
                    mma16816(acc[mt][nt], al[mt], bfr);
                    mma16816(acc[mt][nt], ah[mt], blr);
                }
            }
        }

        // store prefetched chunk c+1 into the OTHER stage (no conflict with stage s reads)
        if (c + 1 < nch) {
            char* const st = smraw + (s ^ 1) * 65536;
            #pragma unroll
            for (int i = 0; i < 2; i++) {
                *(uint4*)(st + soff[i])         = rah[i];
                *(uint4*)(st + 16384 + soff[i]) = ral[i];
                *(uint4*)(st + 32768 + soff[i]) = rbh[i];
                *(uint4*)(st + 49152 + soff[i]) = rbl[i];
            }
        }
        // load chunk c+2 into registers
        if (c + 2 < nch) {
            const __nv_bfloat16* ahn = Ahp + (c + 2) * 64;
            const __nv_bfloat16* aln = Alp + (c + 2) * 64;
            const __nv_bfloat16* bhn = Bhp + (c + 2) * 64;
            const __nv_bfloat16* bln = Blp + (c + 2) * 64;
            #pragma unroll
            for (int i = 0; i < 2; i++) {
                rah[i] = *(const uint4*)(ahn + i * 8);
                ral[i] = *(const uint4*)(aln + i * 8);
                rbh[i] = bval ? *(const uint4*)(bhn + i * 8) : zero4;
                rbl[i] = bval ? *(const uint4*)(bln + i * 8) : zero4;
            }
        }
        __syncthreads();   // one barrier per chunk
    }

    #pragma unroll
    for (int mt = 0; mt < 2; mt++) {
        #pragma unroll
        for (int nt = 0; nt < 4; nt++) {
            int mrow = m0 + wm + mt * 16 + (lane >> 2);
            int ncol = n0 + wn + nt * 8 + 2 * (lane & 3);
            float* d = acc[mt][nt];
            if (ncol < N) {
                long o0 = (long)mrow * N + ncol;
                long o1 = (long)(mrow + 8) * N + ncol;
                if (mode & 4) {
                    C[o0] = d[0]; C[o0 + 1] = d[1];
                    C[o1] = d[2]; C[o1 + 1] = d[3];
                } else {
                    atomicAdd(&C[o0],     d[0]);
                    atomicAdd(&C[o0 + 1], d[1]);
                    atomicAdd(&C[o1],     d[2]);
                    atomicAdd(&C[o1 + 1], d[3]);
                }
            }
        }
    }
}

// ---------------- fused small kernels ----------------
__global__ void rmsnorm_k(const float* __restrict__ X, const float* __restrict__ w,
                          float* __restrict__ Yf,
                          __nv_bfloat16* __restrict__ Hh, __nv_bfloat16* __restrict__ Hl)
{
    int row = blockIdx.x;
    const float* xr = X + (long)row*DM;
    float s = 0.f;
    for (int c = threadIdx.x; c < DM; c += 256) { float v = xr[c]; s = fmaf(v, v, s); }
    __shared__ float red[256];
    red[threadIdx.x] = s; __syncthreads();
    for (int o = 128; o > 0; o >>= 1) {
        if (threadIdx.x < o) red[threadIdx.x] += red[threadIdx.x + o];
        __syncthreads();
    }
    float scale = rsqrtf(red[0] * (1.0f/DM) + 1e-5f);
    for (int c = threadIdx.x; c < DM; c += 256) {
        float v = xr[c] * scale * w[c];
        if (Yf) Yf[(long)row*DM + c] = v;
        if (Hh) {
            __nv_bfloat16 h, l; split1(v, h, l);
            Hh[(long)row*DM + c] = h;
            Hl[(long)row*DM + c] = l;
        }
    }
}

__global__ void conv_silu_k(const float* __restrict__ xz, const float* __restrict__ cw,
                            const float* __restrict__ cb, float* __restrict__ xc,
                            __nv_bfloat16* __restrict__ Hh, __nv_bfloat16* __restrict__ Hl)
{
    int d   = blockIdx.x*256 + threadIdx.x;
    int row = blockIdx.y;
    int l   = row & (SL-1);
    const float4 w4 = *(const float4*)(cw + d*4);
    float acc = cb[d];
    if (l >= 3) acc = fmaf(xz[(long)(row-3)*2*DI + d], w4.x, acc);
    if (l >= 2) acc = fmaf(xz[(long)(row-2)*2*DI + d], w4.y, acc);
    if (l >= 1) acc = fmaf(xz[(long)(row-1)*2*DI + d], w4.z, acc);
    acc = fmaf(xz[(long)row*2*DI + d], w4.w, acc);
    float sig = 1.f / (1.f + __expf(-acc));
    float v = acc * sig;
    long o = (long)row*DI + d;
    xc[o] = v;
    __nv_bfloat16 h, lo; split1(v, h, lo);
    Hh[o] = h; Hl[o] = lo;
}

__global__ void dt_epi_k(float* __restrict__ dt, const float* __restrict__ dtb,
                         const float* __restrict__ xc, float* __restrict__ u,
                         __nv_bfloat16* __restrict__ Hh, __nv_bfloat16* __restrict__ Hl)
{
    int i = blockIdx.x*256 + threadIdx.x;
    int d = i % DI;
    float x = dt[i] + dtb[d];
    float sp = (x > 20.f) ? x : log1pf(__expf(x));
    dt[i] = sp;
    float uv = sp * xc[i];
    u[i] = uv;
    __nv_bfloat16 h, l; split1(uv, h, l);
    Hh[i] = h; Hl[i] = l;
}

// ---------------- w_t = sum_{s<t} beta^{t-1-s} P[s,t] b_s ----------------
__global__ void wk_k(const float* __restrict__ P, const float* __restrict__ xdbl,
                     float* __restrict__ W)
{
    int t = blockIdx.x, b = blockIdx.y, tid = threadIdx.x;
    const float* Prow = P + ((long)b*SL + t)*SL;
    float acc[16];
    #pragma unroll
    for (int n = 0; n < 16; n++) acc[n] = 0.f;

    float decay = exp2f((float)tid * -0.15200309344504995f);
    const float step = 1.3901084526083426e-06f;
    for (int s = t - 1 - tid; s >= 0; s -= 128) {
        float p = Prow[s] * decay;
        const float* bm = xdbl + ((long)b*SL + s)*XD + DR;
        float4 b0 = *(const float4*)(bm);
        float4 b1 = *(const float4*)(bm + 4);
        float4 b2 = *(const float4*)(bm + 8);
        float4 b3 = *(const float4*)(bm + 12);
        acc[0]=fmaf(p,b0.x,acc[0]);  acc[1]=fmaf(p,b0.y,acc[1]);
        acc[2]=fmaf(p,b0.z,acc[2]);  acc[3]=fmaf(p,b0.w,acc[3]);
        acc[4]=fmaf(p,b1.x,acc[4]);  acc[5]=fmaf(p,b1.y,acc[5]);
        acc[6]=fmaf(p,b1.z,acc[6]);  acc[7]=fmaf(p,b1.w,acc[7]);
        acc[8]=fmaf(p,b2.x,acc[8]);  acc[9]=fmaf(p,b2.y,acc[9]);
        acc[10]=fmaf(p,b2.z,acc[10]); acc[11]=fmaf(p,b2.w,acc[11]);
        acc[12]=fmaf(p,b3.x,acc[12]); acc[13]=fmaf(p,b3.y,acc[13]);
        acc[14]=fmaf(p,b3.z,acc[14]); acc[15]=fmaf(p,b3.w,acc[15]);
        decay *= step;
    }
    __shared__ float red[128][17];
    #pragma unroll
    for (int n = 0; n < 16; n++) red[tid][n] = acc[n];
    __syncthreads();
    for (int o = 64; o > 0; o >>= 1) {
        if (tid < o) {
            #pragma unroll
            for (int n = 0; n < 16; n++) red[tid][n] += red[tid+o][n];
        }
        __syncthreads();
    }
    if (tid < 16) W[((long)b*SL + t)*DS + tid] = red[0][tid];
}

// ---------------- G scan (Kogge-Stone over t, decay beta^2) ----------------
__global__ void gscan_k(const float* __restrict__ xdbl, const float* __restrict__ W,
                        const float* __restrict__ P, float* __restrict__ G)
{
    int nm = blockIdx.x;
    int b  = blockIdx.y;
    int n  = nm >> 4, m = nm & 15;
    int t  = threadIdx.x;
    long row = (long)b*SL + t;

    float bn  = xdbl[row*XD + DR + n];
    float bmv = xdbl[row*XD + DR + m];
    float wn  = W[row*DS + n], wm = W[row*DS + m];
    float ptt = P[row*SL + t];
    float g = 0.9f*(bn*wm + wn*bmv) + ptt*bn*bmv;

    __shared__ float sm[SL];
    sm[t] = g; __syncthreads();
    float lam = 0.81f;
    for (int o = 1; o < SL; o <<= 1) {
        float prev = (t >= o) ? sm[t-o] : 0.f;
        __syncthreads();
        g = fmaf(lam, prev, g);
        sm[t] = g;
        __syncthreads();
        lam *= lam;
    }
    G[row*256 + nm] = g;
}

// ---------------- N_t = (aI + b*S + c*S^2)/f ----------------
__global__ void mbuild_k(const float* __restrict__ G, float* __restrict__ Nm)
{
    int bt  = blockIdx.x;
    int tid = threadIdx.x;
    __shared__ float Gs[256], Ss[256];
    __shared__ float fsh;
    Gs[tid] = G[(long)bt*256 + tid];
    __syncthreads();
    if (tid == 0) {
        float tr = 0.f;
        #pragma unroll
        for (int i = 0; i < 16; i++) tr += Gs[i*17];
        fsh = sqrtf(tr) + 1e-7f;
    }
    __syncthreads();
    float f = fsh, fi2 = 1.f/(f*f);
    Ss[tid] = Gs[tid] * fi2;
    __syncthreads();
    int n = tid >> 4, m = tid & 15;
    float s2 = 0.f;
    #pragma unroll
    for (int k = 0; k < 16; k++) s2 = fmaf(Ss[n*16 + k], Ss[k*16 + m], s2);
    float sv = Ss[tid];
    float Mv = fmaf(-4.775f, sv, 2.0315f*s2);
    if (n == m) Mv += 3.4445f;
    Nm[(long)bt*256 + tid] = Mv / f;
}

// ---------------- sequential scan (R12 version: 128 thr, 16 ch/block) --------
__global__ void scan_k(const float* __restrict__ Nm, const float* __restrict__ xdbl,
                       const float* __restrict__ U, const float* __restrict__ DT,
                       const float* __restrict__ A_log, const float* __restrict__ xc,
                       const float* __restrict__ xz, const float* __restrict__ Dp,
                       __nv_bfloat16* __restrict__ Yh, __nv_bfloat16* __restrict__ Yl)
{
    const int b    = blockIdx.y;
    const int tid  = threadIdx.x;            // 128
    const int ch   = blockIdx.x*16 + (tid >> 3);
    const int lane = tid & 7;
    const int n0   = lane*2;

    const float An0 = -__expf(A_log[ch*DS + n0]);
    const float An1 = -__expf(A_log[ch*DS + n0 + 1]);
    const float Dv  = Dp[ch];

    float v0=0.f, v1=0.f, h0=0.f, h1=0.f;
    __shared__ float Ns[2][256];
    __shared__ float bs[2][16], Cs[2][16];
    const float* Nbase = Nm + (long)b*SL*256;
    const long xrow = (long)b*SL*XD + DR;

    float4 nv; float bsv = 0.f, csv = 0.f;
    if (tid < 64) {
        *(float4*)&Ns[0][tid*4] = *(const float4*)(Nbase + tid*4);
        nv = *(const float4*)(Nbase + 256 + tid*4);
    } else if (tid < 80) {
        bs[0][tid-64] = xdbl[xrow + (tid-64)];
        bsv = xdbl[xrow + XD + (tid-64)];
    } else if (tid < 96) {
        Cs[0][tid-80] = xdbl[xrow + DS + (tid-80)];
        csv = xdbl[xrow + XD + DS + (tid-80)];
    }
    const long base_di = (long)b*SL*DI + ch;
    const long base_z  = (long)b*SL*2*DI + DI + ch;
    float uCur  = U [base_di],      dtCur = DT[base_di];
    float xcCur = xc[base_di],      zCur  = xz[base_z];
    float uNxt  = U [base_di + DI], dtNxt = DT[base_di + DI];
    float xcNxt = xc[base_di + DI], zNxt  = xz[base_z + 2*DI];
    __syncthreads();

    for (int t = 0; t < SL; t++) {
        const int p = t & 1;
        if (t + 1 < SL) {
            if (tid < 64)       *(float4*)&Ns[p^1][tid*4] = nv;
            else if (tid < 80)  bs[p^1][tid-64] = bsv;
            else if (tid < 96)  Cs[p^1][tid-80] = csv;
        }
        if (t + 2 < SL) {
            if (tid < 64)       nv  = *(const float4*)(Nbase + (long)(t+2)*256 + tid*4);
            else if (tid < 80)  bsv = xdbl[xrow + (long)(t+2)*XD + (tid-64)];
            else if (tid < 96)  csv = xdbl[xrow + (long)(t+2)*XD + DS + (tid-80)];
        }
        const float ut = uCur, dtt = dtCur, xcv = xcCur, zv = zCur;
        uCur = uNxt; dtCur = dtNxt; xcCur = xcNxt; zCur = zNxt;
        if (t + 2 < SL) {
            uNxt  = U [base_di + (long)(t+2)*DI];
            dtNxt = DT[base_di + (long)(t+2)*DI];
            xcNxt = xc[base_di + (long)(t+2)*DI];
            zNxt  = xz[base_z + (long)(t+2)*2*DI];
        }

        v0 = fmaf(0.9f, v0, ut*bs[p][n0]);
        v1 = fmaf(0.9f, v1, ut*bs[p][n0+1]);

        float a0 = 0.f, a1 = 0.f;
        #pragma unroll
        for (int j = 0; j < 8; j++) {
            float vm0 = __shfl_sync(0xffffffffu, v0, j, 8);
            float vm1 = __shfl_sync(0xffffffffu, v1, j, 8);
            float2 r0 = *(const float2*)&Ns[p][(2*j)*16 + n0];
            float2 r1 = *(const float2*)&Ns[p][(2*j+1)*16 + n0];
            a0 = fmaf(vm0, r0.x, a0); a1 = fmaf(vm0, r0.y, a1);
            a0 = fmaf(vm1, r1.x, a0); a1 = fmaf(vm1, r1.y, a1);
        }
        float dA0 = __expf(dtt*An0), dA1 = __expf(dtt*An1);
        h0 = fmaf(dA0, h0, a0);
        h1 = fmaf(dA1, h1, a1);

        float yl = h0*Cs[p][n0] + h1*Cs[p][n0+1];
        yl += __shfl_xor_sync(0xffffffffu, yl, 4, 8);
        yl += __shfl_xor_sync(0xffffffffu, yl, 2, 8);
        yl += __shfl_xor_sync(0xffffffffu, yl, 1, 8);
        if (lane == 0) {
            float sig = 1.f / (1.f + __expf(-zv));
            float yv = (yl + Dv*xcv) * (zv*sig);
            __nv_bfloat16 hh, ll; split1(yv, hh, ll);
            long o = base_di + (long)t*DI;
            Yh[o] = hh; Yl[o] = ll;
        }
        __syncthreads();
    }
}

// ---------------- launcher ----------------
extern "C" void kernel_launch(void* const* d_in, const int* in_sizes, int n_in,
                              void* d_out, int out_size)
{
    const float* x    = (const float*)d_in[0];
    const float* inw  = (const float*)d_in[1];
    const float* cw   = (const float*)d_in[2];
    const float* cb   = (const float*)d_in[3];
    const float* xpw  = (const float*)d_in[4];
    const float* dtw  = (const float*)d_in[5];
    const float* dtb  = (const float*)d_in[6];
    const float* alog = (const float*)d_in[7];
    const float* Dpar = (const float*)d_in[8];
    const float* outw = (const float*)d_in[9];
    const float* nw   = (const float*)d_in[10];
    const float* fnw  = (const float*)d_in[11];
    float* out = (float*)d_out;

    float *xres,*xz,*xc,*xdbl,*dt,*u,*P,*W,*G,*Mm;
    __nv_bfloat16 *Ah,*Al,*Bh,*Bl,*xdh,*xdl,*dwh,*dwl;
    cudaGetSymbolAddress((void**)&xres, g_xres);
    cudaGetSymbolAddress((void**)&xz,   g_xz);
    cudaGetSymbolAddress((void**)&xc,   g_xc);
    cudaGetSymbolAddress((void**)&xdbl, g_xdbl);
    cudaGetSymbolAddress((void**)&dt,   g_dt);
    cudaGetSymbolAddress((void**)&u,    g_u);
    cudaGetSymbolAddress((void**)&P,    g_P);
    cudaGetSymbolAddress((void**)&W,    g_W);
    cudaGetSymbolAddress((void**)&G,    g_G);
    cudaGetSymbolAddress((void**)&Mm,   g_M);
    cudaGetSymbolAddress((void**)&Ah,   g_Ah);
    cudaGetSymbolAddress((void**)&Al,   g_Al);
    cudaGetSymbolAddress((void**)&Bh,   g_Bh);
    cudaGetSymbolAddress((void**)&Bl,   g_Bl);
    cudaGetSymbolAddress((void**)&xdh,  g_xdh);
    cudaGetSymbolAddress((void**)&xdl,  g_xdl);
    cudaGetSymbolAddress((void**)&dwh,  g_dwh);
    cudaGetSymbolAddress((void**)&dwl,  g_dwl);

    cudaFuncSetAttribute(hgemm_nt, cudaFuncAttributeMaxDynamicSharedMemorySize, HG_SMEM);

    copy_k<<<(BL*DM + 255)/256, 256>>>(x, xres, BL*DM);

    const int nz = BL*2*DI/4 + BL*XD/4 + NB*SL*SL/4;

    for (int layer = 0; layer < 2; layer++) {
        const float* inw_l  = inw  + (long)layer*2*DI*DM;
        const float* cw_l   = cw   + (long)layer*DI*4;
        const float* cb_l   = cb   + (long)layer*DI;
        const float* xpw_l  = xpw  + (long)layer*XD*DI;
        const float* dtw_l  = dtw  + (long)layer*DI*DR;
        const float* dtb_l  = dtb  + (long)layer*DI;
        const float* alog_l = alog + (long)layer*DI*DS;
        const float* Dp_l   = Dpar + (long)layer*DI;
        const float* outw_l = outw + (long)layer*DM*DI;
        const float* nw_l   = nw   + (long)layer*DM;

        rmsnorm_k<<<BL, 256>>>(xres, nw_l, nullptr, Ah, Al);
        split_k<<<(2*DI*DM/4 + 255)/256, 256>>>((const float4*)inw_l, (uint2*)Bh, (uint2*)Bl, 2*DI*DM/4);
        zero3_k<<<(nz + 255)/256, 256>>>((float4*)xz, BL*2*DI/4,
                                         (float4*)xdbl, BL*XD/4,
                                         (float4*)P, NB*SL*SL/4);
        // xz += xn @ in_w^T : M=1024, N=3072, K=768, split-K 2
        hgemm_nt<<<dim3(2*DI/128, BL/128, 2), 512, HG_SMEM>>>(
            Ah, Al, Bh, Bl, xz, BL, 2*DI, 384, DM, DM, 0, 0, 0, 0, 2);

        conv_silu_k<<<dim3(DI/256, BL), 256>>>(xz, cw_l, cb_l, xc, Ah, Al);

        split_k<<<(XD*DI/4 + 255)/256, 256>>>((const float4*)xpw_l, (uint2*)Bh, (uint2*)Bl, XD*DI/4);
        // xdbl += xc @ xp_w^T : M=1024, N=80, K=1536, split-K 6
        hgemm_nt<<<dim3(1, BL/128, 6), 512, HG_SMEM>>>(
            Ah, Al, Bh, Bl, xdbl, BL, XD, 256, DI, DI, 0, 0, 0, 0, 6);

        // dt = dt_lr @ dtp_w^T : M=1024, N=1536, K=48 padded to 64 (tensor, direct store)
        split_k<<<(BL*XD/4 + 255)/256, 256>>>((const float4*)xdbl, (uint2*)xdh, (uint2*)xdl, BL*XD/4);
        split_pad_k<<<(DI*64 + 255)/256, 256>>>(dtw_l, dwh, dwl);
        hgemm_nt<<<dim3(DI/128, BL/128, 1), 512, HG_SMEM>>>(
            xdh, xdl, dwh, dwl, dt, BL, DI, 64, XD, 64, 0, 0, 0, 4, 1);

        dt_epi_k<<<BL*DI/256, 256>>>(dt, dtb_l, xc, u, Ah, Al);

        // P += U U^T : M=N=512, K=1536, batched NB, lower-tri, split-K 4
        hgemm_nt<<<dim3(SL/128, SL/128, NB*4), 512, HG_SMEM>>>(
            Ah, Al, Ah, Al, P, SL, SL, 384, DI, DI,
            (long)SL*DI, (long)SL*DI, (long)SL*SL, 2, 4);

        wk_k<<<dim3(SL, NB), 128>>>(P, xdbl, W);
        gscan_k<<<dim3(256, NB), 512>>>(xdbl, W, P, G);
        mbuild_k<<<NB*SL, 256>>>(G, Mm);
        scan_k<<<dim3(DI/16, NB), 128>>>(Mm, xdbl, u, dt, alog_l, xc, xz, Dp_l, Ah, Al);

        split_k<<<(DM*DI/4 + 255)/256, 256>>>((const float4*)outw_l, (uint2*)Bh, (uint2*)Bl, DM*DI/4);
        // xres += y @ out_w^T : M=1024, N=768, K=1536, split-K 3 (residual in place)
        hgemm_nt<<<dim3(DM/128, BL/128, 3), 512, HG_SMEM>>>(
            Ah, Al, Bh, Bl, xres, BL, DM, 512, DI, DI, 0, 0, 0, 0, 3);
    }

    rmsnorm_k<<<BL, 256>>>(xres, fnw, out, nullptr, nullptr);
}